// round 8
// baseline (speedup 1.0000x reference)
#include <cuda_runtime.h>
#include <cuda_bf16.h>
#include <cstdint>

// ============================================================================
// AlignmentContrastiveLoss — length-aware dense-packed INT8 mma.sync GEMM
// R8: pack ONLY valid rows/cols (device-side next-fit bin packing of whole
//     images into 144-row M-tiles / whole sentences into 128-col N-tiles).
//     Useful work 9.2GF vs 61.6GF padded -> ~3.3x fewer tiles (~620 vs 1632).
//     Whole-item packing keeps max-over-i CTA-local and gives each (b,c) a
//     unique writer CTA (plain stores to g_S). Epilogue clamps each per-b
//     column max with 0 iff im_l<36 (ref's where(valid,.,0).max semantics).
// ============================================================================

static constexpr int NB  = 128;
static constexpr int DIM = 1024;
static constexpr int MAXMT = 43;   // next-fit bound: closed tile >= 109 rows, 4608/109+1
static constexpr int MAXNT = 82;   // closed tile >= 79 cols, 6400/79+1
static constexpr int AROWS = MAXMT * 144;   // 6192
static constexpr int BROWS = MAXNT * 128;   // 10496

static constexpr float QSCALE = 25.0f;
static constexpr float INV2   = 1.0f / (25.0f * 25.0f);

__device__ __align__(16) int8_t g_A[AROWS * DIM];
__device__ __align__(16) int8_t g_B[BROWS * DIM];
__device__ float g_S[NB * NB];

// packing metadata
__device__ int16_t g_row_b[AROWS];    // global b per packed A row (-1 pad)
__device__ uint8_t g_row_i[AROWS];
__device__ uint8_t g_rowseg[AROWS];   // local segment id in tile (0xFF pad)
__device__ int16_t g_col_c[BROWS];
__device__ uint8_t g_col_j[BROWS];
__device__ uint8_t g_colseg[BROWS];
__device__ int16_t g_tile_b[MAXMT * 36];
__device__ int16_t g_tile_c[MAXNT * 26];
__device__ uint8_t g_tile_nb[MAXMT];
__device__ uint8_t g_tile_nc[MAXNT];
__device__ int g_nmt, g_nnt;

// ---------------------------------------------------------------------------
__device__ __forceinline__ uint32_t smem_u32(const void* p) {
    uint32_t a;
    asm("{ .reg .u64 t; cvta.to.shared.u64 t, %1; cvt.u32.u64 %0, t; }" : "=r"(a) : "l"(p));
    return a;
}
__device__ __forceinline__ void cpa16(uint32_t dst, const void* src) {
    asm volatile("cp.async.cg.shared.global [%0], [%1], 16;" :: "r"(dst), "l"(src));
}
#define CPA_COMMIT() asm volatile("cp.async.commit_group;" ::: "memory")
#define CPA_WAIT1()  asm volatile("cp.async.wait_group 1;" ::: "memory")
#define CPA_WAIT0()  asm volatile("cp.async.wait_group 0;" ::: "memory")

__device__ __forceinline__ uint32_t lds32(uint32_t a) {
    uint32_t v;
    asm volatile("ld.shared.b32 %0, [%1];" : "=r"(v) : "r"(a));
    return v;
}
__device__ __forceinline__ void mma_s8(int& d0, int& d1, int& d2, int& d3,
                                       uint32_t a0, uint32_t a1, uint32_t a2, uint32_t a3,
                                       uint32_t b0, uint32_t b1) {
    asm volatile(
        "mma.sync.aligned.m16n8k32.row.col.s32.s8.s8.s32 "
        "{%0,%1,%2,%3}, {%4,%5,%6,%7}, {%8,%9}, {%0,%1,%2,%3};"
        : "+r"(d0), "+r"(d1), "+r"(d2), "+r"(d3)
        : "r"(a0), "r"(a1), "r"(a2), "r"(a3), "r"(b0), "r"(b1));
}
__device__ __forceinline__ int q8(float v) {
    return __float2int_rn(fminf(fmaxf(v * QSCALE, -127.f), 127.f));
}

// ---------------------------------------------------------------------------
// Stage 0: metadata — next-fit packing + row/col maps
// ---------------------------------------------------------------------------
__global__ void meta_kernel(const int* __restrict__ im_len, const int* __restrict__ s_len) {
    __shared__ int16_t btile[NB], boff[NB], ctile[NB], coff[NB];
    __shared__ uint8_t bseg[NB], cseg[NB];
    const int tid = threadIdx.x;

    // phase 0: init pads
    for (int r = tid; r < AROWS; r += blockDim.x) { g_row_b[r] = -1; g_rowseg[r] = 0xFF; }
    for (int r = tid; r < BROWS; r += blockDim.x) { g_col_c[r] = -1; g_colseg[r] = 0xFF; }
    for (int r = tid; r < MAXMT * 36; r += blockDim.x) g_tile_b[r] = 0;
    for (int r = tid; r < MAXNT * 26; r += blockDim.x) g_tile_c[r] = 0;
    for (int r = tid; r < MAXMT; r += blockDim.x) g_tile_nb[r] = 0;
    for (int r = tid; r < MAXNT; r += blockDim.x) g_tile_nc[r] = 0;
    __syncthreads();

    // phase 1: serial next-fit scans
    if (tid == 0) {
        int tile = 0, off = 0, seg = 0;
        for (int b = 0; b < NB; ++b) {
            int L = im_len[b] - 1;
            if (off + L > 144) { ++tile; off = 0; seg = 0; }
            btile[b] = (int16_t)tile; boff[b] = (int16_t)off; bseg[b] = (uint8_t)seg;
            g_tile_b[tile * 36 + seg] = (int16_t)b;
            off += L; ++seg; g_tile_nb[tile] = (uint8_t)seg;
        }
        g_nmt = tile + 1;
        tile = 0; off = 0; seg = 0;
        for (int c = 0; c < NB; ++c) {
            int L = s_len[c] - 3;
            if (off + L > 128) { ++tile; off = 0; seg = 0; }
            ctile[c] = (int16_t)tile; coff[c] = (int16_t)off; cseg[c] = (uint8_t)seg;
            g_tile_c[tile * 26 + seg] = (int16_t)c;
            off += L; ++seg; g_tile_nc[tile] = (uint8_t)seg;
        }
        g_nnt = tile + 1;
    }
    __syncthreads();

    // phase 2: parallel map fill
    if (tid < NB) {
        int b = tid, L = im_len[b] - 1;
        int base = btile[b] * 144 + boff[b];
        for (int i = 0; i < L; ++i) {
            g_row_b[base + i] = (int16_t)b;
            g_row_i[base + i] = (uint8_t)i;
            g_rowseg[base + i] = bseg[b];
        }
    } else if (tid < 2 * NB) {
        int c = tid - NB, L = s_len[c] - 3;
        int base = ctile[c] * 128 + coff[c];
        for (int j = 0; j < L; ++j) {
            g_col_c[base + j] = (int16_t)c;
            g_col_j[base + j] = (uint8_t)j;
            g_colseg[base + j] = cseg[c];
        }
    }
}

// ---------------------------------------------------------------------------
// Stage 1: pack fp32 -> s8 through the maps (one block per packed row)
// ---------------------------------------------------------------------------
__global__ void pack_kernel(const float* __restrict__ im, const float* __restrict__ sq) {
    const int row = blockIdx.x;
    const int tid = threadIdx.x;

    if (row < 16) {  // zero g_S
        reinterpret_cast<float4*>(g_S)[row * 256 + tid] = make_float4(0.f, 0.f, 0.f, 0.f);
    }

    const float* src = nullptr;
    int8_t* dst;
    if (row < AROWS) {
        dst = g_A + (size_t)row * DIM;
        int b = g_row_b[row];
        if (b >= 0) src = im + (size_t)(b * 37 + g_row_i[row] + 1) * DIM;
    } else {
        int rb = row - AROWS;
        dst = g_B + (size_t)rb * DIM;
        int c = g_col_c[rb];
        if (c >= 0) src = sq + (size_t)(c * 53 + g_col_j[rb] + 1) * DIM;
    }
    const int k = tid * 4;
    uint32_t packed = 0u;
    if (src) {
        float4 v = *reinterpret_cast<const float4*>(src + k);
        int q0 = q8(v.x), q1 = q8(v.y), q2 = q8(v.z), q3 = q8(v.w);
        packed = (uint32_t)(q0 & 0xFF) | ((uint32_t)(q1 & 0xFF) << 8) |
                 ((uint32_t)(q2 & 0xFF) << 16) | ((uint32_t)(q3 & 0xFF) << 24);
    }
    *reinterpret_cast<uint32_t*>(dst + k) = packed;
}

// ---------------------------------------------------------------------------
// Stage 2: s8 mma.sync GEMM (144x128 tile) + segment-aware epilogue
// ---------------------------------------------------------------------------
static constexpr int STAGE_BYTES = 21760;
static constexpr int ROW_BYTES   = 80;
static constexpr int B_SM_OFF    = 11520;
static constexpr int SM_PAIRS    = 38592;   // after red[144][67] f32
static constexpr int SM_RSEG     = 38592 + 3744;         // rowseg_sm[144] u8
static constexpr int SM_SEGB     = SM_RSEG + 144;        // segb[36] i16 (72B)
static constexpr int SM_SEGCL    = SM_SEGB + 72;         // segclamp[36] u8
static constexpr int NCH = 16;

__global__ __launch_bounds__(384, 2)
void mma_kernel(const int* __restrict__ im_len, const int* __restrict__ s_len) {
    if ((int)blockIdx.x >= g_nmt || (int)blockIdx.y >= g_nnt) return;
    __shared__ __align__(16) char sm[43584];
    const uint32_t sb = smem_u32(sm);
    const int tid  = threadIdx.x;
    const int lane = tid & 31;
    const int wid  = tid >> 5;
    const int mt = blockIdx.x;
    const int nt = blockIdx.y;

    const int8_t* Ap = g_A + (size_t)mt * (144 * DIM);
    const int8_t* Bp = g_B + (size_t)nt * (128 * DIM);

    auto load_stage = [&](int stage, int chunk) {
        const int k0 = chunk * 64;
        const uint32_t base = sb + stage * STAGE_BYTES;
        #pragma unroll
        for (int it = 0; it < 3; ++it) {
            int idx = tid + it * 384;
            if (idx < 576) {
                int row = idx >> 2, seg = idx & 3;
                cpa16(base + row * ROW_BYTES + seg * 16, Ap + row * DIM + k0 + seg * 16);
            } else if (idx < 1088) {
                int u = idx - 576;
                int row = u >> 2, seg = u & 3;
                cpa16(base + B_SM_OFF + row * ROW_BYTES + seg * 16, Bp + row * DIM + k0 + seg * 16);
            }
        }
    };

    const int wm = wid >> 2;
    const int wn = wid & 3;
    const int group = lane >> 2;
    const int tig   = lane & 3;
    const int mbase = wm * 48;
    const int nbase = wn * 32;

    int acc[3][4][4];
    #pragma unroll
    for (int mi = 0; mi < 3; ++mi)
        #pragma unroll
        for (int ni = 0; ni < 4; ++ni)
            #pragma unroll
            for (int q = 0; q < 4; ++q) acc[mi][ni][q] = 0;

    load_stage(0, 0); CPA_COMMIT();
    load_stage(1, 1); CPA_COMMIT();

    for (int ch = 0; ch < NCH; ++ch) {
        CPA_WAIT1();
        __syncthreads();
        const uint32_t As = sb + (ch & 1) * STAGE_BYTES;
        const uint32_t Bs = As + B_SM_OFF;
        #pragma unroll
        for (int kk = 0; kk < 2; ++kk) {
            const uint32_t kb = kk * 32;
            uint32_t a[3][4];
            #pragma unroll
            for (int mi = 0; mi < 3; ++mi) {
                uint32_t r0 = As + (mbase + mi * 16 + group) * ROW_BYTES + kb + tig * 4;
                uint32_t r1 = r0 + 8 * ROW_BYTES;
                a[mi][0] = lds32(r0);
                a[mi][1] = lds32(r1);
                a[mi][2] = lds32(r0 + 16);
                a[mi][3] = lds32(r1 + 16);
            }
            #pragma unroll
            for (int ni = 0; ni < 4; ++ni) {
                uint32_t rb = Bs + (nbase + ni * 8 + group) * ROW_BYTES + kb + tig * 4;
                uint32_t b0 = lds32(rb);
                uint32_t b1 = lds32(rb + 16);
                #pragma unroll
                for (int mi = 0; mi < 3; ++mi)
                    mma_s8(acc[mi][ni][0], acc[mi][ni][1], acc[mi][ni][2], acc[mi][ni][3],
                           a[mi][0], a[mi][1], a[mi][2], a[mi][3], b0, b1);
            }
        }
        __syncthreads();
        if (ch + 2 < NCH) load_stage(ch & 1, ch + 2);
        CPA_COMMIT();
    }
    CPA_WAIT0();
    __syncthreads();

    // ---------------- epilogue ----------------
    float*   red   = reinterpret_cast<float*>(sm);               // [144][67]
    float*   pairS = reinterpret_cast<float*>(sm + SM_PAIRS);    // [36][26]
    uint8_t* rseg  = reinterpret_cast<uint8_t*>(sm + SM_RSEG);   // [144]
    int16_t* segb  = reinterpret_cast<int16_t*>(sm + SM_SEGB);   // [36]
    uint8_t* segcl = reinterpret_cast<uint8_t*>(sm + SM_SEGCL);  // [36]

    for (int i = tid; i < 36 * 26; i += 384) pairS[i] = 0.f;
    if (tid < 144) rseg[tid] = g_rowseg[mt * 144 + tid];
    if (tid >= 160 && tid < 196) {
        int s = tid - 160;
        int b = g_tile_b[mt * 36 + s];
        segb[s] = (int16_t)b;
        segcl[s] = (__ldg(&im_len[b]) - 1 < 36) ? 1 : 0;
    }

    #pragma unroll
    for (int h = 0; h < 2; ++h) {
        __syncthreads();
        if ((wn >> 1) == h) {
            #pragma unroll
            for (int mi = 0; mi < 3; ++mi)
                #pragma unroll
                for (int half = 0; half < 2; ++half) {
                    const int r = mbase + mi * 16 + group + half * 8;
                    #pragma unroll
                    for (int ni = 0; ni < 4; ++ni) {
                        int col = nbase + ni * 8 + tig * 2 - h * 64;
                        red[r * 67 + col]     = (float)acc[mi][ni][half * 2 + 0] * INV2;
                        red[r * 67 + col + 1] = (float)acc[mi][ni][half * 2 + 1] * INV2;
                    }
                }
        }
        __syncthreads();

        if (tid < 64) {
            const int colq = tid;
            const int cs = g_colseg[nt * 128 + h * 64 + colq];
            if (cs != 0xFF) {
                float m = -3.4e38f;
                int prev = 0xFF;
                for (int r = 0; r < 144; ++r) {
                    int s = rseg[r];
                    if (s != prev) {
                        if (prev != 0xFF) {
                            float mm = segcl[prev] ? fmaxf(m, 0.f) : m;
                            atomicAdd(&pairS[prev * 26 + cs], mm);
                        }
                        if (s == 0xFF) { prev = 0xFF; break; }
                        prev = s; m = -3.4e38f;
                    }
                    m = fmaxf(m, red[r * 67 + colq]);
                }
                if (prev != 0xFF) {
                    float mm = segcl[prev] ? fmaxf(m, 0.f) : m;
                    atomicAdd(&pairS[prev * 26 + cs], mm);
                }
            }
        }
    }
    __syncthreads();

    // unique-writer final store (each (b,c) lives in exactly one CTA)
    const int nb = g_tile_nb[mt];
    const int nc = g_tile_nc[nt];
    for (int idx = tid; idx < nb * nc; idx += 384) {
        int s = idx / nc, cs = idx - s * nc;
        int b = segb[s];
        int c = g_tile_c[nt * 26 + cs];
        g_S[b * NB + c] = pairS[s * 26 + cs];
    }
}

// ---------------------------------------------------------------------------
// Stage 3: hinge-loss reduction over S (128x128)
// ---------------------------------------------------------------------------
__global__ void loss_kernel(float* __restrict__ out) {
    __shared__ float diag[NB];
    __shared__ float wsum[8];
    const int tid = threadIdx.x;
    if (tid < NB) diag[tid] = g_S[tid * (NB + 1)];
    __syncthreads();
    float acc = 0.f;
    for (int idx = tid; idx < NB * NB; idx += 256) {
        int b = idx >> 7, c = idx & 127;
        if (b != c) {
            float sc = g_S[idx];
            acc += fmaxf(0.f, 0.2f + sc - diag[b]) + fmaxf(0.f, 0.2f + sc - diag[c]);
        }
    }
    #pragma unroll
    for (int o = 16; o; o >>= 1) acc += __shfl_xor_sync(0xffffffffu, acc, o);
    if ((tid & 31) == 0) wsum[tid >> 5] = acc;
    __syncthreads();
    if (tid < 8) {
        float v = wsum[tid];
        #pragma unroll
        for (int o = 4; o; o >>= 1) v += __shfl_xor_sync(0xffu, v, o);
        if (tid == 0) out[0] = v;
    }
}

// ---------------------------------------------------------------------------
extern "C" void kernel_launch(void* const* d_in, const int* in_sizes, int n_in,
                              void* d_out, int out_size) {
    (void)in_sizes; (void)n_in; (void)out_size;
    const float* im   = (const float*)d_in[0];
    const float* sq   = (const float*)d_in[1];
    const int* im_len = (const int*)d_in[2];
    const int* s_len  = (const int*)d_in[3];

    meta_kernel<<<1, 256>>>(im_len, s_len);
    pack_kernel<<<AROWS + BROWS, 256>>>(im, sq);
    mma_kernel<<<dim3(MAXMT, MAXNT), 384>>>(im_len, s_len);
    loss_kernel<<<1, 256>>>((float*)d_out);
}

// round 10
// speedup vs baseline: 1.0637x; 1.0637x over previous
#include <cuda_runtime.h>
#include <cuda_bf16.h>
#include <cstdint>

// ============================================================================
// AlignmentContrastiveLoss — length-aware packed INT8 mma.sync, persistent CTAs
// R10: identical to R9 (infra failed twice; no signal). Bin-packing kept; the
//     mma kernel is a persistent-CTA work loop (grid = 296 = 148 SMs x occ2,
//     tiles via atomic ticket) -- eliminates ~2900 empty-CTA launches and
//     ragged waves that made R8 launch-structure-bound.
// ============================================================================

static constexpr int NB  = 128;
static constexpr int DIM = 1024;
static constexpr int MAXMT = 43;
static constexpr int MAXNT = 82;
static constexpr int AROWS = MAXMT * 144;   // 6192
static constexpr int BROWS = MAXNT * 128;   // 10496

static constexpr float QSCALE = 25.0f;
static constexpr float INV2   = 1.0f / (25.0f * 25.0f);

__device__ __align__(16) int8_t g_A[AROWS * DIM];
__device__ __align__(16) int8_t g_B[BROWS * DIM];
__device__ float g_S[NB * NB];

// packing metadata
__device__ int16_t g_row_b[AROWS];
__device__ uint8_t g_row_i[AROWS];
__device__ uint8_t g_rowseg[AROWS];
__device__ int16_t g_col_c[BROWS];
__device__ uint8_t g_col_j[BROWS];
__device__ uint8_t g_colseg[BROWS];
__device__ int16_t g_tile_b[MAXMT * 36];
__device__ int16_t g_tile_c[MAXNT * 26];
__device__ uint8_t g_tile_nb[MAXMT];
__device__ uint8_t g_tile_nc[MAXNT];
__device__ int g_nmt, g_nnt, g_T, g_tick;

// ---------------------------------------------------------------------------
__device__ __forceinline__ uint32_t smem_u32(const void* p) {
    uint32_t a;
    asm("{ .reg .u64 t; cvta.to.shared.u64 t, %1; cvt.u32.u64 %0, t; }" : "=r"(a) : "l"(p));
    return a;
}
__device__ __forceinline__ void cpa16(uint32_t dst, const void* src) {
    asm volatile("cp.async.cg.shared.global [%0], [%1], 16;" :: "r"(dst), "l"(src));
}
#define CPA_COMMIT() asm volatile("cp.async.commit_group;" ::: "memory")
#define CPA_WAIT1()  asm volatile("cp.async.wait_group 1;" ::: "memory")
#define CPA_WAIT0()  asm volatile("cp.async.wait_group 0;" ::: "memory")

__device__ __forceinline__ uint32_t lds32(uint32_t a) {
    uint32_t v;
    asm volatile("ld.shared.b32 %0, [%1];" : "=r"(v) : "r"(a));
    return v;
}
__device__ __forceinline__ void mma_s8(int& d0, int& d1, int& d2, int& d3,
                                       uint32_t a0, uint32_t a1, uint32_t a2, uint32_t a3,
                                       uint32_t b0, uint32_t b1) {
    asm volatile(
        "mma.sync.aligned.m16n8k32.row.col.s32.s8.s8.s32 "
        "{%0,%1,%2,%3}, {%4,%5,%6,%7}, {%8,%9}, {%0,%1,%2,%3};"
        : "+r"(d0), "+r"(d1), "+r"(d2), "+r"(d3)
        : "r"(a0), "r"(a1), "r"(a2), "r"(a3), "r"(b0), "r"(b1));
}
__device__ __forceinline__ int q8(float v) {
    return __float2int_rn(fminf(fmaxf(v * QSCALE, -127.f), 127.f));
}

// ---------------------------------------------------------------------------
// Stage 0: metadata — next-fit packing + row/col maps + ticket reset
// ---------------------------------------------------------------------------
__global__ void meta_kernel(const int* __restrict__ im_len, const int* __restrict__ s_len) {
    __shared__ int16_t btile[NB], boff[NB], ctile[NB], coff[NB];
    __shared__ uint8_t bseg[NB], cseg[NB];
    const int tid = threadIdx.x;

    for (int r = tid; r < AROWS; r += blockDim.x) { g_row_b[r] = -1; g_rowseg[r] = 0xFF; }
    for (int r = tid; r < BROWS; r += blockDim.x) { g_col_c[r] = -1; g_colseg[r] = 0xFF; }
    for (int r = tid; r < MAXMT * 36; r += blockDim.x) g_tile_b[r] = 0;
    for (int r = tid; r < MAXNT * 26; r += blockDim.x) g_tile_c[r] = 0;
    for (int r = tid; r < MAXMT; r += blockDim.x) g_tile_nb[r] = 0;
    for (int r = tid; r < MAXNT; r += blockDim.x) g_tile_nc[r] = 0;
    if (tid == 32) g_tick = 0;
    __syncthreads();

    if (tid == 0) {
        int tile = 0, off = 0, seg = 0;
        for (int b = 0; b < NB; ++b) {
            int L = im_len[b] - 1;
            if (off + L > 144) { ++tile; off = 0; seg = 0; }
            btile[b] = (int16_t)tile; boff[b] = (int16_t)off; bseg[b] = (uint8_t)seg;
            g_tile_b[tile * 36 + seg] = (int16_t)b;
            off += L; ++seg; g_tile_nb[tile] = (uint8_t)seg;
        }
        int nmt = tile + 1;
        g_nmt = nmt;
        tile = 0; off = 0; seg = 0;
        for (int c = 0; c < NB; ++c) {
            int L = s_len[c] - 3;
            if (off + L > 128) { ++tile; off = 0; seg = 0; }
            ctile[c] = (int16_t)tile; coff[c] = (int16_t)off; cseg[c] = (uint8_t)seg;
            g_tile_c[tile * 26 + seg] = (int16_t)c;
            off += L; ++seg; g_tile_nc[tile] = (uint8_t)seg;
        }
        int nnt = tile + 1;
        g_nnt = nnt;
        g_T = nmt * nnt;
    }
    __syncthreads();

    if (tid < NB) {
        int b = tid, L = im_len[b] - 1;
        int base = btile[b] * 144 + boff[b];
        for (int i = 0; i < L; ++i) {
            g_row_b[base + i] = (int16_t)b;
            g_row_i[base + i] = (uint8_t)i;
            g_rowseg[base + i] = bseg[b];
        }
    } else if (tid < 2 * NB) {
        int c = tid - NB, L = s_len[c] - 3;
        int base = ctile[c] * 128 + coff[c];
        for (int j = 0; j < L; ++j) {
            g_col_c[base + j] = (int16_t)c;
            g_col_j[base + j] = (uint8_t)j;
            g_colseg[base + j] = cseg[c];
        }
    }
}

// ---------------------------------------------------------------------------
// Stage 1: pack fp32 -> s8 through the maps (skip rows beyond used tiles)
// ---------------------------------------------------------------------------
__global__ void pack_kernel(const float* __restrict__ im, const float* __restrict__ sq) {
    const int row = blockIdx.x;
    const int tid = threadIdx.x;

    if (row < 16) {  // zero g_S
        reinterpret_cast<float4*>(g_S)[row * 256 + tid] = make_float4(0.f, 0.f, 0.f, 0.f);
    }

    const float* src = nullptr;
    int8_t* dst;
    if (row < AROWS) {
        if (row >= g_nmt * 144) return;          // unused tile: never read
        dst = g_A + (size_t)row * DIM;
        int b = g_row_b[row];
        if (b >= 0) src = im + (size_t)(b * 37 + g_row_i[row] + 1) * DIM;
    } else {
        int rb = row - AROWS;
        if (rb >= g_nnt * 128) return;
        dst = g_B + (size_t)rb * DIM;
        int c = g_col_c[rb];
        if (c >= 0) src = sq + (size_t)(c * 53 + g_col_j[rb] + 1) * DIM;
    }
    const int k = tid * 4;
    uint32_t packed = 0u;
    if (src) {
        float4 v = *reinterpret_cast<const float4*>(src + k);
        int q0 = q8(v.x), q1 = q8(v.y), q2 = q8(v.z), q3 = q8(v.w);
        packed = (uint32_t)(q0 & 0xFF) | ((uint32_t)(q1 & 0xFF) << 8) |
                 ((uint32_t)(q2 & 0xFF) << 16) | ((uint32_t)(q3 & 0xFF) << 24);
    }
    *reinterpret_cast<uint32_t*>(dst + k) = packed;
}

// ---------------------------------------------------------------------------
// Stage 2: persistent-CTA s8 mma.sync GEMM + segment-aware epilogue
// ---------------------------------------------------------------------------
static constexpr int STAGE_BYTES = 21760;
static constexpr int ROW_BYTES   = 80;
static constexpr int B_SM_OFF    = 11520;
static constexpr int SM_PAIRS    = 38592;                 // [36][26] f32 (aliases stage1)
static constexpr int SM_RSEG     = 38592 + 3744;          // [144] u8
static constexpr int SM_SEGB     = SM_RSEG + 144;         // [36] i16
static constexpr int SM_SEGCL    = SM_SEGB + 72;          // [36] u8
static constexpr int SM_TIDX     = 43544;                 // int (outside stages)
static constexpr int NCH = 16;
static constexpr int PCTAS = 296;                         // 148 SMs x occ 2

__global__ __launch_bounds__(384, 2)
void mma_kernel(const int* __restrict__ im_len, const int* __restrict__ s_len) {
    __shared__ __align__(16) char sm[43584];
    const uint32_t sb = smem_u32(sm);
    const int tid  = threadIdx.x;
    const int lane = tid & 31;
    const int wid  = tid >> 5;

    const int wm = wid >> 2;
    const int wn = wid & 3;
    const int group = lane >> 2;
    const int tig   = lane & 3;
    const int mbase = wm * 48;
    const int nbase = wn * 32;

    const int nnt = g_nnt;
    const int T   = g_T;
    int* s_t = reinterpret_cast<int*>(sm + SM_TIDX);

    for (;;) {
        if (tid == 0) *s_t = atomicAdd(&g_tick, 1);
        __syncthreads();
        const int t = *s_t;
        if (t >= T) break;
        const int mt = t / nnt;
        const int nt = t - mt * nnt;

        const int8_t* Ap = g_A + (size_t)mt * (144 * DIM);
        const int8_t* Bp = g_B + (size_t)nt * (128 * DIM);

        auto load_stage = [&](int stage, int chunk) {
            const int k0 = chunk * 64;
            const uint32_t base = sb + stage * STAGE_BYTES;
            #pragma unroll
            for (int it = 0; it < 3; ++it) {
                int idx = tid + it * 384;
                if (idx < 576) {
                    int row = idx >> 2, seg = idx & 3;
                    cpa16(base + row * ROW_BYTES + seg * 16, Ap + row * DIM + k0 + seg * 16);
                } else if (idx < 1088) {
                    int u = idx - 576;
                    int row = u >> 2, seg = u & 3;
                    cpa16(base + B_SM_OFF + row * ROW_BYTES + seg * 16, Bp + row * DIM + k0 + seg * 16);
                }
            }
        };

        int acc[3][4][4];
        #pragma unroll
        for (int mi = 0; mi < 3; ++mi)
            #pragma unroll
            for (int ni = 0; ni < 4; ++ni)
                #pragma unroll
                for (int q = 0; q < 4; ++q) acc[mi][ni][q] = 0;

        load_stage(0, 0); CPA_COMMIT();
        load_stage(1, 1); CPA_COMMIT();

        for (int ch = 0; ch < NCH; ++ch) {
            CPA_WAIT1();
            __syncthreads();
            const uint32_t As = sb + (ch & 1) * STAGE_BYTES;
            const uint32_t Bs = As + B_SM_OFF;
            #pragma unroll
            for (int kk = 0; kk < 2; ++kk) {
                const uint32_t kb = kk * 32;
                uint32_t a[3][4];
                #pragma unroll
                for (int mi = 0; mi < 3; ++mi) {
                    uint32_t r0 = As + (mbase + mi * 16 + group) * ROW_BYTES + kb + tig * 4;
                    uint32_t r1 = r0 + 8 * ROW_BYTES;
                    a[mi][0] = lds32(r0);
                    a[mi][1] = lds32(r1);
                    a[mi][2] = lds32(r0 + 16);
                    a[mi][3] = lds32(r1 + 16);
                }
                #pragma unroll
                for (int ni = 0; ni < 4; ++ni) {
                    uint32_t rb = Bs + (nbase + ni * 8 + group) * ROW_BYTES + kb + tig * 4;
                    uint32_t b0 = lds32(rb);
                    uint32_t b1 = lds32(rb + 16);
                    #pragma unroll
                    for (int mi = 0; mi < 3; ++mi)
                        mma_s8(acc[mi][ni][0], acc[mi][ni][1], acc[mi][ni][2], acc[mi][ni][3],
                               a[mi][0], a[mi][1], a[mi][2], a[mi][3], b0, b1);
                }
            }
            __syncthreads();
            if (ch + 2 < NCH) load_stage(ch & 1, ch + 2);
            CPA_COMMIT();
        }
        CPA_WAIT0();
        __syncthreads();

        // ---------------- epilogue ----------------
        float*   red   = reinterpret_cast<float*>(sm);
        float*   pairS = reinterpret_cast<float*>(sm + SM_PAIRS);
        uint8_t* rseg  = reinterpret_cast<uint8_t*>(sm + SM_RSEG);
        int16_t* segb  = reinterpret_cast<int16_t*>(sm + SM_SEGB);
        uint8_t* segcl = reinterpret_cast<uint8_t*>(sm + SM_SEGCL);

        for (int i = tid; i < 36 * 26; i += 384) pairS[i] = 0.f;
        if (tid < 144) rseg[tid] = g_rowseg[mt * 144 + tid];
        if (tid >= 160 && tid < 196) {
            int s = tid - 160;
            int b = g_tile_b[mt * 36 + s];
            segb[s] = (int16_t)b;
            segcl[s] = (__ldg(&im_len[b]) - 1 < 36) ? 1 : 0;
        }

        #pragma unroll
        for (int h = 0; h < 2; ++h) {
            __syncthreads();
            if ((wn >> 1) == h) {
                #pragma unroll
                for (int mi = 0; mi < 3; ++mi)
                    #pragma unroll
                    for (int half = 0; half < 2; ++half) {
                        const int r = mbase + mi * 16 + group + half * 8;
                        #pragma unroll
                        for (int ni = 0; ni < 4; ++ni) {
                            int col = nbase + ni * 8 + tig * 2 - h * 64;
                            red[r * 67 + col]     = (float)acc[mi][ni][half * 2 + 0] * INV2;
                            red[r * 67 + col + 1] = (float)acc[mi][ni][half * 2 + 1] * INV2;
                        }
                    }
            }
            __syncthreads();

            if (tid < 64) {
                const int colq = tid;
                const int cs = g_colseg[nt * 128 + h * 64 + colq];
                if (cs != 0xFF) {
                    float m = -3.4e38f;
                    int prev = 0xFF;
                    for (int r = 0; r < 144; ++r) {
                        int s = rseg[r];
                        if (s != prev) {
                            if (prev != 0xFF) {
                                float mm = segcl[prev] ? fmaxf(m, 0.f) : m;
                                atomicAdd(&pairS[prev * 26 + cs], mm);
                            }
                            if (s == 0xFF) { prev = 0xFF; break; }
                            prev = s; m = -3.4e38f;
                        }
                        m = fmaxf(m, red[r * 67 + colq]);
                    }
                    if (prev != 0xFF) {
                        float mm = segcl[prev] ? fmaxf(m, 0.f) : m;
                        atomicAdd(&pairS[prev * 26 + cs], mm);
                    }
                }
            }
        }
        __syncthreads();

        const int nb = g_tile_nb[mt];
        const int nc = g_tile_nc[nt];
        for (int idx = tid; idx < nb * nc; idx += 384) {
            int s = idx / nc, cs = idx - s * nc;
            int b = segb[s];
            int c = g_tile_c[nt * 26 + cs];
            g_S[b * NB + c] = pairS[s * 26 + cs];
        }
        __syncthreads();   // protect smem aliases + s_t before next ticket
    }
}

// ---------------------------------------------------------------------------
// Stage 3: hinge-loss reduction over S (128x128), 1024 threads
// ---------------------------------------------------------------------------
__global__ void loss_kernel(float* __restrict__ out) {
    __shared__ float diag[NB];
    __shared__ float wsum[32];
    const int tid = threadIdx.x;
    if (tid < NB) diag[tid] = g_S[tid * (NB + 1)];
    __syncthreads();
    float acc = 0.f;
    for (int idx = tid; idx < NB * NB; idx += 1024) {
        int b = idx >> 7, c = idx & 127;
        if (b != c) {
            float sc = g_S[idx];
            acc += fmaxf(0.f, 0.2f + sc - diag[b]) + fmaxf(0.f, 0.2f + sc - diag[c]);
        }
    }
    #pragma unroll
    for (int o = 16; o; o >>= 1) acc += __shfl_xor_sync(0xffffffffu, acc, o);
    if ((tid & 31) == 0) wsum[tid >> 5] = acc;
    __syncthreads();
    if (tid < 32) {
        float v = wsum[tid];
        #pragma unroll
        for (int o = 16; o; o >>= 1) v += __shfl_xor_sync(0xffffffffu, v, o);
        if (tid == 0) out[0] = v;
    }
}

// ---------------------------------------------------------------------------
extern "C" void kernel_launch(void* const* d_in, const int* in_sizes, int n_in,
                              void* d_out, int out_size) {
    (void)in_sizes; (void)n_in; (void)out_size;
    const float* im   = (const float*)d_in[0];
    const float* sq   = (const float*)d_in[1];
    const int* im_len = (const int*)d_in[2];
    const int* s_len  = (const int*)d_in[3];

    meta_kernel<<<1, 256>>>(im_len, s_len);
    pack_kernel<<<AROWS + BROWS, 256>>>(im, sq);
    mma_kernel<<<PCTAS, 384>>>(im_len, s_len);
    loss_kernel<<<1, 1024>>>((float*)d_out);
}

// round 11
// speedup vs baseline: 1.0876x; 1.0224x over previous
#include <cuda_runtime.h>
#include <cuda_bf16.h>
#include <cstdint>

// ============================================================================
// AlignmentContrastiveLoss — length-aware packed INT8 mma.sync, persistent CTAs
// R11: (1) meta serial scan reads lengths from SMEM (was ~35us of global
//      pointer-chasing by thread 0); (2) loss fused into mma tail via
//      last-CTA pattern (kills 11.5us launch); (3) launch sequence is now
//      meta,pack,mma so ncu -s 5 finally lands on mma_kernel.
// ============================================================================

static constexpr int NB  = 128;
static constexpr int DIM = 1024;
static constexpr int MAXMT = 43;
static constexpr int MAXNT = 82;
static constexpr int AROWS = MAXMT * 144;   // 6192
static constexpr int BROWS = MAXNT * 128;   // 10496

static constexpr float QSCALE = 25.0f;
static constexpr float INV2   = 1.0f / (25.0f * 25.0f);

__device__ __align__(16) int8_t g_A[AROWS * DIM];
__device__ __align__(16) int8_t g_B[BROWS * DIM];
__device__ float g_S[NB * NB];

// packing metadata
__device__ int16_t g_row_b[AROWS];
__device__ uint8_t g_row_i[AROWS];
__device__ uint8_t g_rowseg[AROWS];
__device__ int16_t g_col_c[BROWS];
__device__ uint8_t g_col_j[BROWS];
__device__ uint8_t g_colseg[BROWS];
__device__ int16_t g_tile_b[MAXMT * 36];
__device__ int16_t g_tile_c[MAXNT * 26];
__device__ uint8_t g_tile_nb[MAXMT];
__device__ uint8_t g_tile_nc[MAXNT];
__device__ int g_nmt, g_nnt, g_T, g_tick, g_done;

// ---------------------------------------------------------------------------
__device__ __forceinline__ uint32_t smem_u32(const void* p) {
    uint32_t a;
    asm("{ .reg .u64 t; cvta.to.shared.u64 t, %1; cvt.u32.u64 %0, t; }" : "=r"(a) : "l"(p));
    return a;
}
__device__ __forceinline__ void cpa16(uint32_t dst, const void* src) {
    asm volatile("cp.async.cg.shared.global [%0], [%1], 16;" :: "r"(dst), "l"(src));
}
#define CPA_COMMIT() asm volatile("cp.async.commit_group;" ::: "memory")
#define CPA_WAIT1()  asm volatile("cp.async.wait_group 1;" ::: "memory")
#define CPA_WAIT0()  asm volatile("cp.async.wait_group 0;" ::: "memory")

__device__ __forceinline__ uint32_t lds32(uint32_t a) {
    uint32_t v;
    asm volatile("ld.shared.b32 %0, [%1];" : "=r"(v) : "r"(a));
    return v;
}
__device__ __forceinline__ void mma_s8(int& d0, int& d1, int& d2, int& d3,
                                       uint32_t a0, uint32_t a1, uint32_t a2, uint32_t a3,
                                       uint32_t b0, uint32_t b1) {
    asm volatile(
        "mma.sync.aligned.m16n8k32.row.col.s32.s8.s8.s32 "
        "{%0,%1,%2,%3}, {%4,%5,%6,%7}, {%8,%9}, {%0,%1,%2,%3};"
        : "+r"(d0), "+r"(d1), "+r"(d2), "+r"(d3)
        : "r"(a0), "r"(a1), "r"(a2), "r"(a3), "r"(b0), "r"(b1));
}
__device__ __forceinline__ int q8(float v) {
    return __float2int_rn(fminf(fmaxf(v * QSCALE, -127.f), 127.f));
}

// ---------------------------------------------------------------------------
// Stage 0: metadata — next-fit packing via SMEM-staged lengths
// ---------------------------------------------------------------------------
__global__ void meta_kernel(const int* __restrict__ im_len, const int* __restrict__ s_len) {
    __shared__ int16_t btile[NB], boff[NB], ctile[NB], coff[NB];
    __shared__ uint8_t bseg[NB], cseg[NB];
    __shared__ int s_iml[NB], s_sl[NB];
    const int tid = threadIdx.x;

    if (tid < NB) s_iml[tid] = im_len[tid];
    else if (tid < 2 * NB) s_sl[tid - NB] = s_len[tid - NB];

    for (int r = tid; r < AROWS; r += blockDim.x) { g_row_b[r] = -1; g_rowseg[r] = 0xFF; }
    for (int r = tid; r < BROWS; r += blockDim.x) { g_col_c[r] = -1; g_colseg[r] = 0xFF; }
    for (int r = tid; r < MAXMT * 36; r += blockDim.x) g_tile_b[r] = 0;
    for (int r = tid; r < MAXNT * 26; r += blockDim.x) g_tile_c[r] = 0;
    for (int r = tid; r < MAXMT; r += blockDim.x) g_tile_nb[r] = 0;
    for (int r = tid; r < MAXNT; r += blockDim.x) g_tile_nc[r] = 0;
    if (tid == 32) { g_tick = 0; g_done = 0; }
    __syncthreads();

    if (tid == 0) {
        int tile = 0, off = 0, seg = 0;
        for (int b = 0; b < NB; ++b) {
            int L = s_iml[b] - 1;
            if (off + L > 144) { ++tile; off = 0; seg = 0; }
            btile[b] = (int16_t)tile; boff[b] = (int16_t)off; bseg[b] = (uint8_t)seg;
            g_tile_b[tile * 36 + seg] = (int16_t)b;
            off += L; ++seg; g_tile_nb[tile] = (uint8_t)seg;
        }
        int nmt = tile + 1;
        g_nmt = nmt;
        tile = 0; off = 0; seg = 0;
        for (int c = 0; c < NB; ++c) {
            int L = s_sl[c] - 3;
            if (off + L > 128) { ++tile; off = 0; seg = 0; }
            ctile[c] = (int16_t)tile; coff[c] = (int16_t)off; cseg[c] = (uint8_t)seg;
            g_tile_c[tile * 26 + seg] = (int16_t)c;
            off += L; ++seg; g_tile_nc[tile] = (uint8_t)seg;
        }
        int nnt = tile + 1;
        g_nnt = nnt;
        g_T = nmt * nnt;
    }
    __syncthreads();

    if (tid < NB) {
        int b = tid, L = s_iml[b] - 1;
        int base = btile[b] * 144 + boff[b];
        for (int i = 0; i < L; ++i) {
            g_row_b[base + i] = (int16_t)b;
            g_row_i[base + i] = (uint8_t)i;
            g_rowseg[base + i] = bseg[b];
        }
    } else if (tid < 2 * NB) {
        int c = tid - NB, L = s_sl[c - 0 + tid - NB - (tid - NB)] - 3;  // = s_sl[c] - 3
        L = s_sl[c] - 3;
        int base = ctile[c] * 128 + coff[c];
        for (int j = 0; j < L; ++j) {
            g_col_c[base + j] = (int16_t)c;
            g_col_j[base + j] = (uint8_t)j;
            g_colseg[base + j] = cseg[c];
        }
    }
}

// ---------------------------------------------------------------------------
// Stage 1: pack fp32 -> s8 through the maps (skip rows beyond used tiles)
// ---------------------------------------------------------------------------
__global__ void pack_kernel(const float* __restrict__ im, const float* __restrict__ sq) {
    const int row = blockIdx.x;
    const int tid = threadIdx.x;

    if (row < 16) {  // zero g_S
        reinterpret_cast<float4*>(g_S)[row * 256 + tid] = make_float4(0.f, 0.f, 0.f, 0.f);
    }

    const float* src = nullptr;
    int8_t* dst;
    if (row < AROWS) {
        if (row >= g_nmt * 144) return;
        dst = g_A + (size_t)row * DIM;
        int b = g_row_b[row];
        if (b >= 0) src = im + (size_t)(b * 37 + g_row_i[row] + 1) * DIM;
    } else {
        int rb = row - AROWS;
        if (rb >= g_nnt * 128) return;
        dst = g_B + (size_t)rb * DIM;
        int c = g_col_c[rb];
        if (c >= 0) src = sq + (size_t)(c * 53 + g_col_j[rb] + 1) * DIM;
    }
    const int k = tid * 4;
    uint32_t packed = 0u;
    if (src) {
        float4 v = *reinterpret_cast<const float4*>(src + k);
        int q0 = q8(v.x), q1 = q8(v.y), q2 = q8(v.z), q3 = q8(v.w);
        packed = (uint32_t)(q0 & 0xFF) | ((uint32_t)(q1 & 0xFF) << 8) |
                 ((uint32_t)(q2 & 0xFF) << 16) | ((uint32_t)(q3 & 0xFF) << 24);
    }
    *reinterpret_cast<uint32_t*>(dst + k) = packed;
}

// ---------------------------------------------------------------------------
// Stage 2: persistent-CTA s8 mma.sync GEMM + epilogue + fused last-CTA loss
// ---------------------------------------------------------------------------
static constexpr int STAGE_BYTES = 21760;
static constexpr int ROW_BYTES   = 80;
static constexpr int B_SM_OFF    = 11520;
static constexpr int SM_PAIRS    = 38592;
static constexpr int SM_RSEG     = 38592 + 3744;
static constexpr int SM_SEGB     = SM_RSEG + 144;
static constexpr int SM_SEGCL    = SM_SEGB + 72;
static constexpr int SM_TIDX     = 43544;
static constexpr int NCH = 16;
static constexpr int PCTAS = 296;

__global__ __launch_bounds__(384, 2)
void mma_kernel(const int* __restrict__ im_len, const int* __restrict__ s_len,
                float* __restrict__ out) {
    __shared__ __align__(16) char sm[43584];
    const uint32_t sb = smem_u32(sm);
    const int tid  = threadIdx.x;
    const int lane = tid & 31;
    const int wid  = tid >> 5;

    const int wm = wid >> 2;
    const int wn = wid & 3;
    const int group = lane >> 2;
    const int tig   = lane & 3;
    const int mbase = wm * 48;
    const int nbase = wn * 32;

    const int nnt = g_nnt;
    const int T   = g_T;
    int* s_t = reinterpret_cast<int*>(sm + SM_TIDX);

    for (;;) {
        if (tid == 0) *s_t = atomicAdd(&g_tick, 1);
        __syncthreads();
        const int t = *s_t;
        if (t >= T) break;
        const int mt = t / nnt;
        const int nt = t - mt * nnt;

        const int8_t* Ap = g_A + (size_t)mt * (144 * DIM);
        const int8_t* Bp = g_B + (size_t)nt * (128 * DIM);

        auto load_stage = [&](int stage, int chunk) {
            const int k0 = chunk * 64;
            const uint32_t base = sb + stage * STAGE_BYTES;
            #pragma unroll
            for (int it = 0; it < 3; ++it) {
                int idx = tid + it * 384;
                if (idx < 576) {
                    int row = idx >> 2, seg = idx & 3;
                    cpa16(base + row * ROW_BYTES + seg * 16, Ap + row * DIM + k0 + seg * 16);
                } else if (idx < 1088) {
                    int u = idx - 576;
                    int row = u >> 2, seg = u & 3;
                    cpa16(base + B_SM_OFF + row * ROW_BYTES + seg * 16, Bp + row * DIM + k0 + seg * 16);
                }
            }
        };

        int acc[3][4][4];
        #pragma unroll
        for (int mi = 0; mi < 3; ++mi)
            #pragma unroll
            for (int ni = 0; ni < 4; ++ni)
                #pragma unroll
                for (int q = 0; q < 4; ++q) acc[mi][ni][q] = 0;

        load_stage(0, 0); CPA_COMMIT();
        load_stage(1, 1); CPA_COMMIT();

        for (int ch = 0; ch < NCH; ++ch) {
            CPA_WAIT1();
            __syncthreads();
            const uint32_t As = sb + (ch & 1) * STAGE_BYTES;
            const uint32_t Bs = As + B_SM_OFF;
            #pragma unroll
            for (int kk = 0; kk < 2; ++kk) {
                const uint32_t kb = kk * 32;
                uint32_t a[3][4];
                #pragma unroll
                for (int mi = 0; mi < 3; ++mi) {
                    uint32_t r0 = As + (mbase + mi * 16 + group) * ROW_BYTES + kb + tig * 4;
                    uint32_t r1 = r0 + 8 * ROW_BYTES;
                    a[mi][0] = lds32(r0);
                    a[mi][1] = lds32(r1);
                    a[mi][2] = lds32(r0 + 16);
                    a[mi][3] = lds32(r1 + 16);
                }
                #pragma unroll
                for (int ni = 0; ni < 4; ++ni) {
                    uint32_t rb = Bs + (nbase + ni * 8 + group) * ROW_BYTES + kb + tig * 4;
                    uint32_t b0 = lds32(rb);
                    uint32_t b1 = lds32(rb + 16);
                    #pragma unroll
                    for (int mi = 0; mi < 3; ++mi)
                        mma_s8(acc[mi][ni][0], acc[mi][ni][1], acc[mi][ni][2], acc[mi][ni][3],
                               a[mi][0], a[mi][1], a[mi][2], a[mi][3], b0, b1);
                }
            }
            __syncthreads();
            if (ch + 2 < NCH) load_stage(ch & 1, ch + 2);
            CPA_COMMIT();
        }
        CPA_WAIT0();
        __syncthreads();

        // ---------------- epilogue ----------------
        float*   red   = reinterpret_cast<float*>(sm);
        float*   pairS = reinterpret_cast<float*>(sm + SM_PAIRS);
        uint8_t* rseg  = reinterpret_cast<uint8_t*>(sm + SM_RSEG);
        int16_t* segb  = reinterpret_cast<int16_t*>(sm + SM_SEGB);
        uint8_t* segcl = reinterpret_cast<uint8_t*>(sm + SM_SEGCL);

        for (int i = tid; i < 36 * 26; i += 384) pairS[i] = 0.f;
        if (tid < 144) rseg[tid] = g_rowseg[mt * 144 + tid];
        if (tid >= 160 && tid < 196) {
            int s = tid - 160;
            int b = g_tile_b[mt * 36 + s];
            segb[s] = (int16_t)b;
            segcl[s] = (__ldg(&im_len[b]) - 1 < 36) ? 1 : 0;
        }

        #pragma unroll
        for (int h = 0; h < 2; ++h) {
            __syncthreads();
            if ((wn >> 1) == h) {
                #pragma unroll
                for (int mi = 0; mi < 3; ++mi)
                    #pragma unroll
                    for (int half = 0; half < 2; ++half) {
                        const int r = mbase + mi * 16 + group + half * 8;
                        #pragma unroll
                        for (int ni = 0; ni < 4; ++ni) {
                            int col = nbase + ni * 8 + tig * 2 - h * 64;
                            red[r * 67 + col]     = (float)acc[mi][ni][half * 2 + 0] * INV2;
                            red[r * 67 + col + 1] = (float)acc[mi][ni][half * 2 + 1] * INV2;
                        }
                    }
            }
            __syncthreads();

            if (tid < 64) {
                const int colq = tid;
                const int cs = g_colseg[nt * 128 + h * 64 + colq];
                if (cs != 0xFF) {
                    float m = -3.4e38f;
                    int prev = 0xFF;
                    for (int r = 0; r < 144; ++r) {
                        int s = rseg[r];
                        if (s != prev) {
                            if (prev != 0xFF) {
                                float mm = segcl[prev] ? fmaxf(m, 0.f) : m;
                                atomicAdd(&pairS[prev * 26 + cs], mm);
                            }
                            if (s == 0xFF) { prev = 0xFF; break; }
                            prev = s; m = -3.4e38f;
                        }
                        m = fmaxf(m, red[r * 67 + colq]);
                    }
                    if (prev != 0xFF) {
                        float mm = segcl[prev] ? fmaxf(m, 0.f) : m;
                        atomicAdd(&pairS[prev * 26 + cs], mm);
                    }
                }
            }
        }
        __syncthreads();

        const int nb = g_tile_nb[mt];
        const int nc = g_tile_nc[nt];
        for (int idx = tid; idx < nb * nc; idx += 384) {
            int s = idx / nc, cs = idx - s * nc;
            int b = segb[s];
            int c = g_tile_c[nt * 26 + cs];
            g_S[b * NB + c] = pairS[s * 26 + cs];
        }
        __syncthreads();
    }

    // ---------------- fused loss: last CTA reduces g_S ----------------
    __threadfence();
    __syncthreads();
    if (tid == 0) {
        int old = atomicAdd(&g_done, 1);
        *s_t = (old == PCTAS - 1) ? 1 : 0;
    }
    __syncthreads();
    if (*s_t) {
        __threadfence();  // order: g_done observation -> g_S loads
        float* diag = reinterpret_cast<float*>(sm);        // [128]
        float* wsum = reinterpret_cast<float*>(sm) + 128;  // [12]
        if (tid < NB) diag[tid] = g_S[tid * (NB + 1)];
        __syncthreads();
        float acc = 0.f;
        for (int idx = tid; idx < NB * NB; idx += 384) {
            int b = idx >> 7, c = idx & 127;
            if (b != c) {
                float sc = g_S[idx];
                acc += fmaxf(0.f, 0.2f + sc - diag[b]) + fmaxf(0.f, 0.2f + sc - diag[c]);
            }
        }
        #pragma unroll
        for (int o = 16; o; o >>= 1) acc += __shfl_xor_sync(0xffffffffu, acc, o);
        if (lane == 0) wsum[wid] = acc;
        __syncthreads();
        if (wid == 0) {
            float v = (lane < 12) ? wsum[lane] : 0.f;
            #pragma unroll
            for (int o = 16; o; o >>= 1) v += __shfl_xor_sync(0xffffffffu, v, o);
            if (lane == 0) out[0] = v;
        }
    }
}

// ---------------------------------------------------------------------------
extern "C" void kernel_launch(void* const* d_in, const int* in_sizes, int n_in,
                              void* d_out, int out_size) {
    (void)in_sizes; (void)n_in; (void)out_size;
    const float* im   = (const float*)d_in[0];
    const float* sq   = (const float*)d_in[1];
    const int* im_len = (const int*)d_in[2];
    const int* s_len  = (const int*)d_in[3];

    meta_kernel<<<1, 256>>>(im_len, s_len);
    pack_kernel<<<AROWS + BROWS, 256>>>(im, sq);
    mma_kernel<<<PCTAS, 384>>>(im_len, s_len, (float*)d_out);
}

// round 13
// speedup vs baseline: 1.6586x; 1.5250x over previous
#include <cuda_runtime.h>
#include <cuda_bf16.h>
#include <cstdint>

// ============================================================================
// AlignmentContrastiveLoss — length-aware packed INT8 mma.sync, persistent CTAs
// R13: identical to R12 (infra failed twice; no signal).
//      (1) meta serial scan touches SMEM only, parallel global fills after
//      (meta 29 -> ~6us); (2) epilogue segment-max parallelized over
//      (col x segment) via g_tile_off/len; (3) red moved to dedicated smem
//      (dynamic 86KB, occ 2) so the next tile's stage loads are issued BEFORE
//      the epilogue -> tile loads overlap epilogue instead of serializing.
// ============================================================================

static constexpr int NB  = 128;
static constexpr int DIM = 1024;
static constexpr int MAXMT = 43;
static constexpr int MAXNT = 82;
static constexpr int AROWS = MAXMT * 144;   // 6192
static constexpr int BROWS = MAXNT * 128;   // 10496

static constexpr float QSCALE = 25.0f;
static constexpr float INV2   = 1.0f / (25.0f * 25.0f);

__device__ __align__(16) int8_t g_A[AROWS * DIM];
__device__ __align__(16) int8_t g_B[BROWS * DIM];
__device__ float g_S[NB * NB];

// packing metadata
__device__ int16_t g_row_b[AROWS];
__device__ uint8_t g_row_i[AROWS];
__device__ int16_t g_col_c[BROWS];
__device__ uint8_t g_col_j[BROWS];
__device__ uint8_t g_colseg[BROWS];
__device__ int16_t g_tile_b[MAXMT * 36];
__device__ int16_t g_tile_off[MAXMT * 36];
__device__ uint8_t g_tile_len[MAXMT * 36];
__device__ int16_t g_tile_c[MAXNT * 26];
__device__ uint8_t g_tile_nb[MAXMT];
__device__ uint8_t g_tile_nc[MAXNT];
__device__ int g_nmt, g_nnt, g_T, g_tick, g_done;

// ---------------------------------------------------------------------------
__device__ __forceinline__ uint32_t smem_u32(const void* p) {
    uint32_t a;
    asm("{ .reg .u64 t; cvta.to.shared.u64 t, %1; cvt.u32.u64 %0, t; }" : "=r"(a) : "l"(p));
    return a;
}
__device__ __forceinline__ void cpa16(uint32_t dst, const void* src) {
    asm volatile("cp.async.cg.shared.global [%0], [%1], 16;" :: "r"(dst), "l"(src));
}
#define CPA_COMMIT() asm volatile("cp.async.commit_group;" ::: "memory")
#define CPA_WAIT1()  asm volatile("cp.async.wait_group 1;" ::: "memory")
#define CPA_WAIT0()  asm volatile("cp.async.wait_group 0;" ::: "memory")

__device__ __forceinline__ uint32_t lds32(uint32_t a) {
    uint32_t v;
    asm volatile("ld.shared.b32 %0, [%1];" : "=r"(v) : "r"(a));
    return v;
}
__device__ __forceinline__ void mma_s8(int& d0, int& d1, int& d2, int& d3,
                                       uint32_t a0, uint32_t a1, uint32_t a2, uint32_t a3,
                                       uint32_t b0, uint32_t b1) {
    asm volatile(
        "mma.sync.aligned.m16n8k32.row.col.s32.s8.s8.s32 "
        "{%0,%1,%2,%3}, {%4,%5,%6,%7}, {%8,%9}, {%0,%1,%2,%3};"
        : "+r"(d0), "+r"(d1), "+r"(d2), "+r"(d3)
        : "r"(a0), "r"(a1), "r"(a2), "r"(a3), "r"(b0), "r"(b1));
}
__device__ __forceinline__ int q8(float v) {
    return __float2int_rn(fminf(fmaxf(v * QSCALE, -127.f), 127.f));
}

// ---------------------------------------------------------------------------
// Stage 0: metadata — serial scan in SMEM only, parallel global fills
// ---------------------------------------------------------------------------
__global__ void meta_kernel(const int* __restrict__ im_len, const int* __restrict__ s_len) {
    __shared__ int16_t btile[NB], boff[NB], ctile[NB], coff[NB];
    __shared__ uint8_t bseg[NB], cseg[NB];
    __shared__ int s_iml[NB], s_sl[NB];
    const int tid = threadIdx.x;

    if (tid < NB) s_iml[tid] = im_len[tid];
    else if (tid < 2 * NB) s_sl[tid - NB] = s_len[tid - NB];

    for (int r = tid; r < AROWS; r += blockDim.x) g_row_b[r] = -1;
    for (int r = tid; r < BROWS; r += blockDim.x) { g_col_c[r] = -1; g_colseg[r] = 0xFF; }
    if (tid == 32) { g_tick = 0; g_done = 0; }
    __syncthreads();

    if (tid == 0) {   // serial next-fit scans: SMEM-only writes
        int tile = 0, off = 0, seg = 0;
        for (int b = 0; b < NB; ++b) {
            int L = s_iml[b] - 1;
            if (off + L > 144) { ++tile; off = 0; seg = 0; }
            btile[b] = (int16_t)tile; boff[b] = (int16_t)off; bseg[b] = (uint8_t)seg;
            off += L; ++seg;
        }
        int nmt = tile + 1;
        g_nmt = nmt;
        tile = 0; off = 0; seg = 0;
        for (int c = 0; c < NB; ++c) {
            int L = s_sl[c] - 3;
            if (off + L > 128) { ++tile; off = 0; seg = 0; }
            ctile[c] = (int16_t)tile; coff[c] = (int16_t)off; cseg[c] = (uint8_t)seg;
            off += L; ++seg;
        }
        int nnt = tile + 1;
        g_nnt = nnt;
        g_T = nmt * nnt;
    }
    __syncthreads();

    if (tid < NB) {                       // image-side parallel fills
        int b = tid, L = s_iml[b] - 1;
        int tl = btile[b], sg = bseg[b], of = boff[b];
        g_tile_b[tl * 36 + sg]   = (int16_t)b;
        g_tile_off[tl * 36 + sg] = (int16_t)of;
        g_tile_len[tl * 36 + sg] = (uint8_t)L;
        if (b == NB - 1 || btile[b + 1] != tl) g_tile_nb[tl] = (uint8_t)(sg + 1);
        int base = tl * 144 + of;
        for (int i = 0; i < L; ++i) {
            g_row_b[base + i] = (int16_t)b;
            g_row_i[base + i] = (uint8_t)i;
        }
    } else if (tid < 2 * NB) {            // sentence-side parallel fills
        int c = tid - NB, L = s_sl[c] - 3;
        int tl = ctile[c], sg = cseg[c], of = coff[c];
        g_tile_c[tl * 26 + sg] = (int16_t)c;
        if (c == NB - 1 || ctile[c + 1] != tl) g_tile_nc[tl] = (uint8_t)(sg + 1);
        int base = tl * 128 + of;
        for (int j = 0; j < L; ++j) {
            g_col_c[base + j]   = (int16_t)c;
            g_col_j[base + j]   = (uint8_t)j;
            g_colseg[base + j]  = (uint8_t)sg;
        }
    }
}

// ---------------------------------------------------------------------------
// Stage 1: pack fp32 -> s8 through the maps (skip rows beyond used tiles)
// ---------------------------------------------------------------------------
__global__ void pack_kernel(const float* __restrict__ im, const float* __restrict__ sq) {
    const int row = blockIdx.x;
    const int tid = threadIdx.x;

    if (row < 16) {  // zero g_S
        reinterpret_cast<float4*>(g_S)[row * 256 + tid] = make_float4(0.f, 0.f, 0.f, 0.f);
    }

    const float* src = nullptr;
    int8_t* dst;
    if (row < AROWS) {
        if (row >= g_nmt * 144) return;
        dst = g_A + (size_t)row * DIM;
        int b = g_row_b[row];
        if (b >= 0) src = im + (size_t)(b * 37 + g_row_i[row] + 1) * DIM;
    } else {
        int rb = row - AROWS;
        if (rb >= g_nnt * 128) return;
        dst = g_B + (size_t)rb * DIM;
        int c = g_col_c[rb];
        if (c >= 0) src = sq + (size_t)(c * 53 + g_col_j[rb] + 1) * DIM;
    }
    const int k = tid * 4;
    uint32_t packed = 0u;
    if (src) {
        float4 v = *reinterpret_cast<const float4*>(src + k);
        int q0 = q8(v.x), q1 = q8(v.y), q2 = q8(v.z), q3 = q8(v.w);
        packed = (uint32_t)(q0 & 0xFF) | ((uint32_t)(q1 & 0xFF) << 8) |
                 ((uint32_t)(q2 & 0xFF) << 16) | ((uint32_t)(q3 & 0xFF) << 24);
    }
    *reinterpret_cast<uint32_t*>(dst + k) = packed;
}

// ---------------------------------------------------------------------------
// Stage 2: persistent-CTA s8 GEMM, prefetched tiles, parallel epilogue, loss
// ---------------------------------------------------------------------------
static constexpr int STAGE_BYTES = 21760;
static constexpr int ROW_BYTES   = 80;
static constexpr int B_SM_OFF    = 11520;
static constexpr int SM_RED      = 43520;               // [144][67] f32 = 38592
static constexpr int SM_PAIRS    = 82112;               // [36][26]  f32 = 3744
static constexpr int SM_SEGB     = 85856;               // [36] i16
static constexpr int SM_SEGCL    = 85928;               // [36] u8
static constexpr int SM_SEGOFF   = 85968;               // [36] i16
static constexpr int SM_SEGLEN   = 86040;               // [36] u8
static constexpr int SM_CS       = 86076;               // [64] u8
static constexpr int SM_TIDX     = 86144;               // int
static constexpr int SMEM_TOTAL  = 86208;
static constexpr int NCH = 16;
static constexpr int PCTAS = 296;

__global__ __launch_bounds__(384, 2)
void mma_kernel(const int* __restrict__ im_len, const int* __restrict__ s_len,
                float* __restrict__ out) {
    extern __shared__ __align__(16) char sm[];
    const uint32_t sb = smem_u32(sm);
    const int tid  = threadIdx.x;
    const int lane = tid & 31;
    const int wid  = tid >> 5;

    const int wm = wid >> 2;
    const int wn = wid & 3;
    const int group = lane >> 2;
    const int tig   = lane & 3;
    const int mbase = wm * 48;
    const int nbase = wn * 32;

    const int nnt = g_nnt;
    const int T   = g_T;
    int* s_t = reinterpret_cast<int*>(sm + SM_TIDX);

    auto load_stage = [&](int stage, int chunk, const int8_t* Ap, const int8_t* Bp) {
        const int k0 = chunk * 64;
        const uint32_t base = sb + stage * STAGE_BYTES;
        #pragma unroll
        for (int it = 0; it < 3; ++it) {
            int idx = tid + it * 384;
            if (idx < 576) {
                int row = idx >> 2, seg = idx & 3;
                cpa16(base + row * ROW_BYTES + seg * 16, Ap + row * DIM + k0 + seg * 16);
            } else if (idx < 1088) {
                int u = idx - 576;
                int row = u >> 2, seg = u & 3;
                cpa16(base + B_SM_OFF + row * ROW_BYTES + seg * 16, Bp + row * DIM + k0 + seg * 16);
            }
        }
    };

    // first ticket + prologue loads
    if (tid == 0) *s_t = atomicAdd(&g_tick, 1);
    __syncthreads();
    int t = *s_t;
    if (t < T) {
        const int mt0 = t / nnt, nt0 = t - (t / nnt) * nnt;
        const int8_t* Ap = g_A + (size_t)mt0 * (144 * DIM);
        const int8_t* Bp = g_B + (size_t)nt0 * (128 * DIM);
        load_stage(0, 0, Ap, Bp); CPA_COMMIT();
        load_stage(1, 1, Ap, Bp); CPA_COMMIT();
    }

    while (t < T) {
        const int mt = t / nnt;
        const int nt = t - mt * nnt;
        const int8_t* Ap = g_A + (size_t)mt * (144 * DIM);
        const int8_t* Bp = g_B + (size_t)nt * (128 * DIM);

        int acc[3][4][4];
        #pragma unroll
        for (int mi = 0; mi < 3; ++mi)
            #pragma unroll
            for (int ni = 0; ni < 4; ++ni)
                #pragma unroll
                for (int q = 0; q < 4; ++q) acc[mi][ni][q] = 0;

        for (int ch = 0; ch < NCH; ++ch) {
            CPA_WAIT1();
            __syncthreads();
            const uint32_t As = sb + (ch & 1) * STAGE_BYTES;
            const uint32_t Bs = As + B_SM_OFF;
            #pragma unroll
            for (int kk = 0; kk < 2; ++kk) {
                const uint32_t kb = kk * 32;
                uint32_t a[3][4];
                #pragma unroll
                for (int mi = 0; mi < 3; ++mi) {
                    uint32_t r0 = As + (mbase + mi * 16 + group) * ROW_BYTES + kb + tig * 4;
                    uint32_t r1 = r0 + 8 * ROW_BYTES;
                    a[mi][0] = lds32(r0);
                    a[mi][1] = lds32(r1);
                    a[mi][2] = lds32(r0 + 16);
                    a[mi][3] = lds32(r1 + 16);
                }
                #pragma unroll
                for (int ni = 0; ni < 4; ++ni) {
                    uint32_t rb = Bs + (nbase + ni * 8 + group) * ROW_BYTES + kb + tig * 4;
                    uint32_t b0 = lds32(rb);
                    uint32_t b1 = lds32(rb + 16);
                    #pragma unroll
                    for (int mi = 0; mi < 3; ++mi)
                        mma_s8(acc[mi][ni][0], acc[mi][ni][1], acc[mi][ni][2], acc[mi][ni][3],
                               a[mi][0], a[mi][1], a[mi][2], a[mi][3], b0, b1);
                }
            }
            __syncthreads();
            if (ch + 2 < NCH) load_stage(ch & 1, ch + 2, Ap, Bp);
            CPA_COMMIT();
        }
        CPA_WAIT0();

        // fetch next ticket and prefetch its first two stages BEFORE epilogue
        if (tid == 0) *s_t = atomicAdd(&g_tick, 1);
        __syncthreads();                    // compute done; s_t published
        const int t2 = *s_t;
        if (t2 < T) {
            const int mt2 = t2 / nnt, nt2 = t2 - (t2 / nnt) * nnt;
            const int8_t* Ap2 = g_A + (size_t)mt2 * (144 * DIM);
            const int8_t* Bp2 = g_B + (size_t)nt2 * (128 * DIM);
            load_stage(0, 0, Ap2, Bp2); CPA_COMMIT();
            load_stage(1, 1, Ap2, Bp2); CPA_COMMIT();
        }

        // ---------------- epilogue (red region disjoint from stages) -------
        float*   red    = reinterpret_cast<float*>(sm + SM_RED);
        float*   pairS  = reinterpret_cast<float*>(sm + SM_PAIRS);
        int16_t* segb   = reinterpret_cast<int16_t*>(sm + SM_SEGB);
        uint8_t* segcl  = reinterpret_cast<uint8_t*>(sm + SM_SEGCL);
        int16_t* segoff = reinterpret_cast<int16_t*>(sm + SM_SEGOFF);
        uint8_t* seglen = reinterpret_cast<uint8_t*>(sm + SM_SEGLEN);
        uint8_t* cs_sm  = reinterpret_cast<uint8_t*>(sm + SM_CS);

        const int nbv = g_tile_nb[mt];
        for (int i = tid; i < 36 * 26; i += 384) pairS[i] = 0.f;
        if (tid < nbv) {
            int s = tid;
            segb[s]   = g_tile_b[mt * 36 + s];
            segoff[s] = g_tile_off[mt * 36 + s];
            int L = g_tile_len[mt * 36 + s];
            seglen[s] = (uint8_t)L;
            segcl[s]  = (L < 36) ? 1 : 0;
        }

        #pragma unroll
        for (int h = 0; h < 2; ++h) {
            if (tid < 64) cs_sm[tid] = g_colseg[nt * 128 + h * 64 + tid];
            __syncthreads();
            if ((wn >> 1) == h) {
                #pragma unroll
                for (int mi = 0; mi < 3; ++mi)
                    #pragma unroll
                    for (int half = 0; half < 2; ++half) {
                        const int r = mbase + mi * 16 + group + half * 8;
                        #pragma unroll
                        for (int ni = 0; ni < 4; ++ni) {
                            int col = nbase + ni * 8 + tig * 2 - h * 64;
                            red[r * 67 + col]     = (float)acc[mi][ni][half * 2 + 0] * INV2;
                            red[r * 67 + col + 1] = (float)acc[mi][ni][half * 2 + 1] * INV2;
                        }
                    }
            }
            __syncthreads();

            const int col = tid & 63;
            const int cs = cs_sm[col];
            if (cs != 0xFF) {
                for (int s = tid >> 6; s < nbv; s += 6) {
                    const int r0 = segoff[s];
                    const int L  = seglen[s];
                    const float* cp = red + r0 * 67 + col;
                    float m = cp[0];
                    for (int r = 1; r < L; ++r) m = fmaxf(m, cp[r * 67]);
                    if (segcl[s]) m = fmaxf(m, 0.f);
                    atomicAdd(&pairS[s * 26 + cs], m);
                }
            }
            __syncthreads();
        }

        const int ncv = g_tile_nc[nt];
        for (int idx = tid; idx < nbv * ncv; idx += 384) {
            int s = idx / ncv, cs = idx - s * ncv;
            int b = segb[s];
            int c = g_tile_c[nt * 26 + cs];
            g_S[b * NB + c] = pairS[s * 26 + cs];
        }
        __syncthreads();
        t = t2;
    }

    // ---------------- fused loss: last CTA reduces g_S ----------------
    __threadfence();
    __syncthreads();
    if (tid == 0) {
        int old = atomicAdd(&g_done, 1);
        *s_t = (old == PCTAS - 1) ? 1 : 0;
    }
    __syncthreads();
    if (*s_t) {
        __threadfence();
        float* diag = reinterpret_cast<float*>(sm);
        float* wsum = reinterpret_cast<float*>(sm) + 128;
        if (tid < NB) diag[tid] = g_S[tid * (NB + 1)];
        __syncthreads();
        float acc = 0.f;
        for (int idx = tid; idx < NB * NB; idx += 384) {
            int b = idx >> 7, c = idx & 127;
            if (b != c) {
                float sc = g_S[idx];
                acc += fmaxf(0.f, 0.2f + sc - diag[b]) + fmaxf(0.f, 0.2f + sc - diag[c]);
            }
        }
        #pragma unroll
        for (int o = 16; o; o >>= 1) acc += __shfl_xor_sync(0xffffffffu, acc, o);
        if (lane == 0) wsum[wid] = acc;
        __syncthreads();
        if (wid == 0) {
            float v = (lane < 12) ? wsum[lane] : 0.f;
            #pragma unroll
            for (int o = 16; o; o >>= 1) v += __shfl_xor_sync(0xffffffffu, v, o);
            if (lane == 0) out[0] = v;
        }
    }
}

// ---------------------------------------------------------------------------
extern "C" void kernel_launch(void* const* d_in, const int* in_sizes, int n_in,
                              void* d_out, int out_size) {
    (void)in_sizes; (void)n_in; (void)out_size;
    const float* im   = (const float*)d_in[0];
    const float* sq   = (const float*)d_in[1];
    const int* im_len = (const int*)d_in[2];
    const int* s_len  = (const int*)d_in[3];

    cudaFuncSetAttribute(mma_kernel, cudaFuncAttributeMaxDynamicSharedMemorySize, SMEM_TOTAL);

    meta_kernel<<<1, 256>>>(im_len, s_len);
    pack_kernel<<<AROWS + BROWS, 256>>>(im, sq);
    mma_kernel<<<PCTAS, 384, SMEM_TOTAL>>>(im_len, s_len, (float*)d_out);
}

// round 14
// speedup vs baseline: 1.8841x; 1.1360x over previous
#include <cuda_runtime.h>
#include <cuda_bf16.h>
#include <cstdint>

// ============================================================================
// AlignmentContrastiveLoss — length-aware packed INT8 mma.sync, persistent CTAs
// R14: meta's big per-row maps DELETED (g_row_b/i, g_col_c/j were ~17K scattered
//      global stores from ONE CTA = ~20us of the 25.8us meta). meta now writes
//      only ~2KB of per-tile segment tables; pack resolves row->(b,i)/(c,j)
//      itself via a parallel segment match (latency hidden across 16.7K blocks)
//      and writes g_colseg as a byproduct. mma kernel identical to R13.
// ============================================================================

static constexpr int NB  = 128;
static constexpr int DIM = 1024;
static constexpr int MAXMT = 43;
static constexpr int MAXNT = 82;
static constexpr int AROWS = MAXMT * 144;   // 6192
static constexpr int BROWS = MAXNT * 128;   // 10496

static constexpr float QSCALE = 25.0f;
static constexpr float INV2   = 1.0f / (25.0f * 25.0f);

__device__ __align__(16) int8_t g_A[AROWS * DIM];
__device__ __align__(16) int8_t g_B[BROWS * DIM];
__device__ float g_S[NB * NB];

// packing metadata (per-tile segment tables only)
__device__ uint8_t g_colseg[BROWS];            // filled by pack
__device__ int16_t g_tile_b[MAXMT * 36];
__device__ int16_t g_tile_off[MAXMT * 36];
__device__ uint8_t g_tile_len[MAXMT * 36];
__device__ int16_t g_tile_c[MAXNT * 26];
__device__ int16_t g_tile_coff[MAXNT * 26];
__device__ uint8_t g_tile_clen[MAXNT * 26];
__device__ uint8_t g_tile_nb[MAXMT];
__device__ uint8_t g_tile_nc[MAXNT];
__device__ int g_nmt, g_nnt, g_T, g_tick, g_done;

// ---------------------------------------------------------------------------
__device__ __forceinline__ uint32_t smem_u32(const void* p) {
    uint32_t a;
    asm("{ .reg .u64 t; cvta.to.shared.u64 t, %1; cvt.u32.u64 %0, t; }" : "=r"(a) : "l"(p));
    return a;
}
__device__ __forceinline__ void cpa16(uint32_t dst, const void* src) {
    asm volatile("cp.async.cg.shared.global [%0], [%1], 16;" :: "r"(dst), "l"(src));
}
#define CPA_COMMIT() asm volatile("cp.async.commit_group;" ::: "memory")
#define CPA_WAIT1()  asm volatile("cp.async.wait_group 1;" ::: "memory")
#define CPA_WAIT0()  asm volatile("cp.async.wait_group 0;" ::: "memory")

__device__ __forceinline__ uint32_t lds32(uint32_t a) {
    uint32_t v;
    asm volatile("ld.shared.b32 %0, [%1];" : "=r"(v) : "r"(a));
    return v;
}
__device__ __forceinline__ void mma_s8(int& d0, int& d1, int& d2, int& d3,
                                       uint32_t a0, uint32_t a1, uint32_t a2, uint32_t a3,
                                       uint32_t b0, uint32_t b1) {
    asm volatile(
        "mma.sync.aligned.m16n8k32.row.col.s32.s8.s8.s32 "
        "{%0,%1,%2,%3}, {%4,%5,%6,%7}, {%8,%9}, {%0,%1,%2,%3};"
        : "+r"(d0), "+r"(d1), "+r"(d2), "+r"(d3)
        : "r"(a0), "r"(a1), "r"(a2), "r"(a3), "r"(b0), "r"(b1));
}
__device__ __forceinline__ int q8(float v) {
    return __float2int_rn(fminf(fmaxf(v * QSCALE, -127.f), 127.f));
}

// ---------------------------------------------------------------------------
// Stage 0: metadata — serial smem scans + O(1)-per-thread table writes (~2KB)
// ---------------------------------------------------------------------------
__global__ void meta_kernel(const int* __restrict__ im_len, const int* __restrict__ s_len) {
    __shared__ int16_t btile[NB], boff[NB], ctile[NB], coff[NB];
    __shared__ uint8_t bseg[NB], cseg[NB];
    __shared__ int s_iml[NB], s_sl[NB];
    const int tid = threadIdx.x;

    if (tid < NB) s_iml[tid] = im_len[tid];
    else if (tid < 2 * NB) s_sl[tid - NB] = s_len[tid - NB];
    if (tid == 32) { g_tick = 0; g_done = 0; }
    __syncthreads();

    if (tid == 0) {   // serial next-fit scans: SMEM-only writes
        int tile = 0, off = 0, seg = 0;
        #pragma unroll 4
        for (int b = 0; b < NB; ++b) {
            int L = s_iml[b] - 1;
            if (off + L > 144) { ++tile; off = 0; seg = 0; }
            btile[b] = (int16_t)tile; boff[b] = (int16_t)off; bseg[b] = (uint8_t)seg;
            off += L; ++seg;
        }
        g_nmt = tile + 1;
    } else if (tid == 64) {
        int tile = 0, off = 0, seg = 0;
        #pragma unroll 4
        for (int c = 0; c < NB; ++c) {
            int L = s_sl[c] - 3;
            if (off + L > 128) { ++tile; off = 0; seg = 0; }
            ctile[c] = (int16_t)tile; coff[c] = (int16_t)off; cseg[c] = (uint8_t)seg;
            off += L; ++seg;
        }
        g_nnt = tile + 1;
    }
    __syncthreads();
    if (tid == 0) g_T = g_nmt * g_nnt;

    if (tid < NB) {                       // image-side table writes (O(1) each)
        int b = tid, L = s_iml[b] - 1;
        int tl = btile[b], sg = bseg[b], of = boff[b];
        g_tile_b[tl * 36 + sg]   = (int16_t)b;
        g_tile_off[tl * 36 + sg] = (int16_t)of;
        g_tile_len[tl * 36 + sg] = (uint8_t)L;
        if (b == NB - 1 || btile[b + 1] != tl) g_tile_nb[tl] = (uint8_t)(sg + 1);
    } else if (tid < 2 * NB) {            // sentence-side table writes
        int c = tid - NB, L = s_sl[c] - 3;
        int tl = ctile[c], sg = cseg[c], of = coff[c];
        g_tile_c[tl * 26 + sg]    = (int16_t)c;
        g_tile_coff[tl * 26 + sg] = (int16_t)of;
        g_tile_clen[tl * 26 + sg] = (uint8_t)L;
        if (c == NB - 1 || ctile[c + 1] != tl) g_tile_nc[tl] = (uint8_t)(sg + 1);
    }
}

// ---------------------------------------------------------------------------
// Stage 1: pack fp32 -> s8; each block resolves its row via segment match
// ---------------------------------------------------------------------------
__global__ void pack_kernel(const float* __restrict__ im, const float* __restrict__ sq) {
    const int row = blockIdx.x;
    const int tid = threadIdx.x;

    if (row < 16) {  // zero g_S
        reinterpret_cast<float4*>(g_S)[row * 256 + tid] = make_float4(0.f, 0.f, 0.f, 0.f);
    }

    __shared__ int s_n, s_sel, s_item, s_pos;

    const float* src = nullptr;
    int8_t* dst;
    if (row < AROWS) {
        if (row >= g_nmt * 144) return;
        const int tl = row / 144, local = row - tl * 144;
        if (tid == 0) { s_n = g_tile_nb[tl]; s_sel = -1; }
        __syncthreads();
        if (tid < s_n) {
            int of = g_tile_off[tl * 36 + tid];
            int L  = g_tile_len[tl * 36 + tid];
            if (local >= of && local < of + L) {
                s_item = g_tile_b[tl * 36 + tid];
                s_pos  = local - of;
                s_sel  = tid;
            }
        }
        __syncthreads();
        dst = g_A + (size_t)row * DIM;
        if (s_sel >= 0) src = im + (size_t)(s_item * 37 + s_pos + 1) * DIM;
    } else {
        const int rb = row - AROWS;
        if (rb >= g_nnt * 128) return;
        const int tl = rb / 128, local = rb - tl * 128;
        if (tid == 0) { s_n = g_tile_nc[tl]; s_sel = -1; }
        __syncthreads();
        if (tid < s_n) {
            int of = g_tile_coff[tl * 26 + tid];
            int L  = g_tile_clen[tl * 26 + tid];
            if (local >= of && local < of + L) {
                s_item = g_tile_c[tl * 26 + tid];
                s_pos  = local - of;
                s_sel  = tid;
            }
        }
        __syncthreads();
        dst = g_B + (size_t)rb * DIM;
        if (s_sel >= 0) src = sq + (size_t)(s_item * 53 + s_pos + 1) * DIM;
        if (tid == 0) g_colseg[rb] = (s_sel >= 0) ? (uint8_t)s_sel : 0xFF;
    }
    const int k = tid * 4;
    uint32_t packed = 0u;
    if (src) {
        float4 v = *reinterpret_cast<const float4*>(src + k);
        int q0 = q8(v.x), q1 = q8(v.y), q2 = q8(v.z), q3 = q8(v.w);
        packed = (uint32_t)(q0 & 0xFF) | ((uint32_t)(q1 & 0xFF) << 8) |
                 ((uint32_t)(q2 & 0xFF) << 16) | ((uint32_t)(q3 & 0xFF) << 24);
    }
    *reinterpret_cast<uint32_t*>(dst + k) = packed;
}

// ---------------------------------------------------------------------------
// Stage 2: persistent-CTA s8 GEMM, prefetched tiles, parallel epilogue, loss
// ---------------------------------------------------------------------------
static constexpr int STAGE_BYTES = 21760;
static constexpr int ROW_BYTES   = 80;
static constexpr int B_SM_OFF    = 11520;
static constexpr int SM_RED      = 43520;               // [144][67] f32 = 38592
static constexpr int SM_PAIRS    = 82112;               // [36][26]  f32 = 3744
static constexpr int SM_SEGB     = 85856;               // [36] i16
static constexpr int SM_SEGCL    = 85928;               // [36] u8
static constexpr int SM_SEGOFF   = 85968;               // [36] i16
static constexpr int SM_SEGLEN   = 86040;               // [36] u8
static constexpr int SM_CS       = 86076;               // [64] u8
static constexpr int SM_TIDX     = 86144;               // int
static constexpr int SMEM_TOTAL  = 86208;
static constexpr int NCH = 16;
static constexpr int PCTAS = 296;

__global__ __launch_bounds__(384, 2)
void mma_kernel(const int* __restrict__ im_len, const int* __restrict__ s_len,
                float* __restrict__ out) {
    extern __shared__ __align__(16) char sm[];
    const uint32_t sb = smem_u32(sm);
    const int tid  = threadIdx.x;
    const int lane = tid & 31;
    const int wid  = tid >> 5;

    const int wm = wid >> 2;
    const int wn = wid & 3;
    const int group = lane >> 2;
    const int tig   = lane & 3;
    const int mbase = wm * 48;
    const int nbase = wn * 32;

    const int nnt = g_nnt;
    const int T   = g_T;
    int* s_t = reinterpret_cast<int*>(sm + SM_TIDX);

    auto load_stage = [&](int stage, int chunk, const int8_t* Ap, const int8_t* Bp) {
        const int k0 = chunk * 64;
        const uint32_t base = sb + stage * STAGE_BYTES;
        #pragma unroll
        for (int it = 0; it < 3; ++it) {
            int idx = tid + it * 384;
            if (idx < 576) {
                int row = idx >> 2, seg = idx & 3;
                cpa16(base + row * ROW_BYTES + seg * 16, Ap + row * DIM + k0 + seg * 16);
            } else if (idx < 1088) {
                int u = idx - 576;
                int row = u >> 2, seg = u & 3;
                cpa16(base + B_SM_OFF + row * ROW_BYTES + seg * 16, Bp + row * DIM + k0 + seg * 16);
            }
        }
    };

    // first ticket + prologue loads
    if (tid == 0) *s_t = atomicAdd(&g_tick, 1);
    __syncthreads();
    int t = *s_t;
    if (t < T) {
        const int mt0 = t / nnt, nt0 = t - (t / nnt) * nnt;
        const int8_t* Ap = g_A + (size_t)mt0 * (144 * DIM);
        const int8_t* Bp = g_B + (size_t)nt0 * (128 * DIM);
        load_stage(0, 0, Ap, Bp); CPA_COMMIT();
        load_stage(1, 1, Ap, Bp); CPA_COMMIT();
    }

    while (t < T) {
        const int mt = t / nnt;
        const int nt = t - mt * nnt;
        const int8_t* Ap = g_A + (size_t)mt * (144 * DIM);
        const int8_t* Bp = g_B + (size_t)nt * (128 * DIM);

        int acc[3][4][4];
        #pragma unroll
        for (int mi = 0; mi < 3; ++mi)
            #pragma unroll
            for (int ni = 0; ni < 4; ++ni)
                #pragma unroll
                for (int q = 0; q < 4; ++q) acc[mi][ni][q] = 0;

        for (int ch = 0; ch < NCH; ++ch) {
            CPA_WAIT1();
            __syncthreads();
            const uint32_t As = sb + (ch & 1) * STAGE_BYTES;
            const uint32_t Bs = As + B_SM_OFF;
            #pragma unroll
            for (int kk = 0; kk < 2; ++kk) {
                const uint32_t kb = kk * 32;
                uint32_t a[3][4];
                #pragma unroll
                for (int mi = 0; mi < 3; ++mi) {
                    uint32_t r0 = As + (mbase + mi * 16 + group) * ROW_BYTES + kb + tig * 4;
                    uint32_t r1 = r0 + 8 * ROW_BYTES;
                    a[mi][0] = lds32(r0);
                    a[mi][1] = lds32(r1);
                    a[mi][2] = lds32(r0 + 16);
                    a[mi][3] = lds32(r1 + 16);
                }
                #pragma unroll
                for (int ni = 0; ni < 4; ++ni) {
                    uint32_t rb = Bs + (nbase + ni * 8 + group) * ROW_BYTES + kb + tig * 4;
                    uint32_t b0 = lds32(rb);
                    uint32_t b1 = lds32(rb + 16);
                    #pragma unroll
                    for (int mi = 0; mi < 3; ++mi)
                        mma_s8(acc[mi][ni][0], acc[mi][ni][1], acc[mi][ni][2], acc[mi][ni][3],
                               a[mi][0], a[mi][1], a[mi][2], a[mi][3], b0, b1);
                }
            }
            __syncthreads();
            if (ch + 2 < NCH) load_stage(ch & 1, ch + 2, Ap, Bp);
            CPA_COMMIT();
        }
        CPA_WAIT0();

        // fetch next ticket and prefetch its first two stages BEFORE epilogue
        if (tid == 0) *s_t = atomicAdd(&g_tick, 1);
        __syncthreads();                    // compute done; s_t published
        const int t2 = *s_t;
        if (t2 < T) {
            const int mt2 = t2 / nnt, nt2 = t2 - (t2 / nnt) * nnt;
            const int8_t* Ap2 = g_A + (size_t)mt2 * (144 * DIM);
            const int8_t* Bp2 = g_B + (size_t)nt2 * (128 * DIM);
            load_stage(0, 0, Ap2, Bp2); CPA_COMMIT();
            load_stage(1, 1, Ap2, Bp2); CPA_COMMIT();
        }

        // ---------------- epilogue (red region disjoint from stages) -------
        float*   red    = reinterpret_cast<float*>(sm + SM_RED);
        float*   pairS  = reinterpret_cast<float*>(sm + SM_PAIRS);
        int16_t* segb   = reinterpret_cast<int16_t*>(sm + SM_SEGB);
        uint8_t* segcl  = reinterpret_cast<uint8_t*>(sm + SM_SEGCL);
        int16_t* segoff = reinterpret_cast<int16_t*>(sm + SM_SEGOFF);
        uint8_t* seglen = reinterpret_cast<uint8_t*>(sm + SM_SEGLEN);
        uint8_t* cs_sm  = reinterpret_cast<uint8_t*>(sm + SM_CS);

        const int nbv = g_tile_nb[mt];
        for (int i = tid; i < 36 * 26; i += 384) pairS[i] = 0.f;
        if (tid < nbv) {
            int s = tid;
            segb[s]   = g_tile_b[mt * 36 + s];
            segoff[s] = g_tile_off[mt * 36 + s];
            int L = g_tile_len[mt * 36 + s];
            seglen[s] = (uint8_t)L;
            segcl[s]  = (L < 36) ? 1 : 0;
        }

        #pragma unroll
        for (int h = 0; h < 2; ++h) {
            if (tid < 64) cs_sm[tid] = g_colseg[nt * 128 + h * 64 + tid];
            __syncthreads();
            if ((wn >> 1) == h) {
                #pragma unroll
                for (int mi = 0; mi < 3; ++mi)
                    #pragma unroll
                    for (int half = 0; half < 2; ++half) {
                        const int r = mbase + mi * 16 + group + half * 8;
                        #pragma unroll
                        for (int ni = 0; ni < 4; ++ni) {
                            int col = nbase + ni * 8 + tig * 2 - h * 64;
                            red[r * 67 + col]     = (float)acc[mi][ni][half * 2 + 0] * INV2;
                            red[r * 67 + col + 1] = (float)acc[mi][ni][half * 2 + 1] * INV2;
                        }
                    }
            }
            __syncthreads();

            const int col = tid & 63;
            const int cs = cs_sm[col];
            if (cs != 0xFF) {
                for (int s = tid >> 6; s < nbv; s += 6) {
                    const int r0 = segoff[s];
                    const int L  = seglen[s];
                    const float* cp = red + r0 * 67 + col;
                    float m = cp[0];
                    for (int r = 1; r < L; ++r) m = fmaxf(m, cp[r * 67]);
                    if (segcl[s]) m = fmaxf(m, 0.f);
                    atomicAdd(&pairS[s * 26 + cs], m);
                }
            }
            __syncthreads();
        }

        const int ncv = g_tile_nc[nt];
        for (int idx = tid; idx < nbv * ncv; idx += 384) {
            int s = idx / ncv, cs = idx - s * ncv;
            int b = segb[s];
            int c = g_tile_c[nt * 26 + cs];
            g_S[b * NB + c] = pairS[s * 26 + cs];
        }
        __syncthreads();
        t = t2;
    }

    // ---------------- fused loss: last CTA reduces g_S ----------------
    __threadfence();
    __syncthreads();
    if (tid == 0) {
        int old = atomicAdd(&g_done, 1);
        *s_t = (old == PCTAS - 1) ? 1 : 0;
    }
    __syncthreads();
    if (*s_t) {
        __threadfence();
        float* diag = reinterpret_cast<float*>(sm);
        float* wsum = reinterpret_cast<float*>(sm) + 128;
        if (tid < NB) diag[tid] = g_S[tid * (NB + 1)];
        __syncthreads();
        float acc = 0.f;
        for (int idx = tid; idx < NB * NB; idx += 384) {
            int b = idx >> 7, c = idx & 127;
            if (b != c) {
                float sc = g_S[idx];
                acc += fmaxf(0.f, 0.2f + sc - diag[b]) + fmaxf(0.f, 0.2f + sc - diag[c]);
            }
        }
        #pragma unroll
        for (int o = 16; o; o >>= 1) acc += __shfl_xor_sync(0xffffffffu, acc, o);
        if (lane == 0) wsum[wid] = acc;
        __syncthreads();
        if (wid == 0) {
            float v = (lane < 12) ? wsum[lane] : 0.f;
            #pragma unroll
            for (int o = 16; o; o >>= 1) v += __shfl_xor_sync(0xffffffffu, v, o);
            if (lane == 0) out[0] = v;
        }
    }
}

// ---------------------------------------------------------------------------
extern "C" void kernel_launch(void* const* d_in, const int* in_sizes, int n_in,
                              void* d_out, int out_size) {
    (void)in_sizes; (void)n_in; (void)out_size;
    const float* im   = (const float*)d_in[0];
    const float* sq   = (const float*)d_in[1];
    const int* im_len = (const int*)d_in[2];
    const int* s_len  = (const int*)d_in[3];

    cudaFuncSetAttribute(mma_kernel, cudaFuncAttributeMaxDynamicSharedMemorySize, SMEM_TOTAL);

    meta_kernel<<<1, 256>>>(im_len, s_len);
    pack_kernel<<<AROWS + BROWS, 256>>>(im, sq);
    mma_kernel<<<PCTAS, 384, SMEM_TOTAL>>>(im_len, s_len, (float*)d_out);
}

// round 15
// speedup vs baseline: 1.8875x; 1.0018x over previous
#include <cuda_runtime.h>
#include <cuda_bf16.h>
#include <cstdint>

// ============================================================================
// AlignmentContrastiveLoss — length-aware packed INT8 mma.sync, persistent CTAs
// R15: mainloop rebuilt as 3-stage single-sync pipeline (chunk k -> stage k%3):
//      per chunk = wait1 -> ONE sync -> issue ch+2 into stage (ch-1)%3 (freed,
//      proven by the sync) -> compute. Halves syncs (32->16/tile) and doubles
//      cp.async latency slack (2 compute-chunks). Epilogue prefetch overlap
//      kept. meta/pack/epilogue/loss identical to R14 (105.4us, rel 3.29e-4).
// ============================================================================

static constexpr int NB  = 128;
static constexpr int DIM = 1024;
static constexpr int MAXMT = 43;
static constexpr int MAXNT = 82;
static constexpr int AROWS = MAXMT * 144;   // 6192
static constexpr int BROWS = MAXNT * 128;   // 10496

static constexpr float QSCALE = 25.0f;
static constexpr float INV2   = 1.0f / (25.0f * 25.0f);

__device__ __align__(16) int8_t g_A[AROWS * DIM];
__device__ __align__(16) int8_t g_B[BROWS * DIM];
__device__ float g_S[NB * NB];

// packing metadata (per-tile segment tables only)
__device__ uint8_t g_colseg[BROWS];            // filled by pack
__device__ int16_t g_tile_b[MAXMT * 36];
__device__ int16_t g_tile_off[MAXMT * 36];
__device__ uint8_t g_tile_len[MAXMT * 36];
__device__ int16_t g_tile_c[MAXNT * 26];
__device__ int16_t g_tile_coff[MAXNT * 26];
__device__ uint8_t g_tile_clen[MAXNT * 26];
__device__ uint8_t g_tile_nb[MAXMT];
__device__ uint8_t g_tile_nc[MAXNT];
__device__ int g_nmt, g_nnt, g_T, g_tick, g_done;

// ---------------------------------------------------------------------------
__device__ __forceinline__ uint32_t smem_u32(const void* p) {
    uint32_t a;
    asm("{ .reg .u64 t; cvta.to.shared.u64 t, %1; cvt.u32.u64 %0, t; }" : "=r"(a) : "l"(p));
    return a;
}
__device__ __forceinline__ void cpa16(uint32_t dst, const void* src) {
    asm volatile("cp.async.cg.shared.global [%0], [%1], 16;" :: "r"(dst), "l"(src));
}
#define CPA_COMMIT() asm volatile("cp.async.commit_group;" ::: "memory")
#define CPA_WAIT1()  asm volatile("cp.async.wait_group 1;" ::: "memory")

__device__ __forceinline__ uint32_t lds32(uint32_t a) {
    uint32_t v;
    asm volatile("ld.shared.b32 %0, [%1];" : "=r"(v) : "r"(a));
    return v;
}
__device__ __forceinline__ void mma_s8(int& d0, int& d1, int& d2, int& d3,
                                       uint32_t a0, uint32_t a1, uint32_t a2, uint32_t a3,
                                       uint32_t b0, uint32_t b1) {
    asm volatile(
        "mma.sync.aligned.m16n8k32.row.col.s32.s8.s8.s32 "
        "{%0,%1,%2,%3}, {%4,%5,%6,%7}, {%8,%9}, {%0,%1,%2,%3};"
        : "+r"(d0), "+r"(d1), "+r"(d2), "+r"(d3)
        : "r"(a0), "r"(a1), "r"(a2), "r"(a3), "r"(b0), "r"(b1));
}
__device__ __forceinline__ int q8(float v) {
    return __float2int_rn(fminf(fmaxf(v * QSCALE, -127.f), 127.f));
}

// ---------------------------------------------------------------------------
// Stage 0: metadata — serial smem scans + O(1)-per-thread table writes (~2KB)
// ---------------------------------------------------------------------------
__global__ void meta_kernel(const int* __restrict__ im_len, const int* __restrict__ s_len) {
    __shared__ int16_t btile[NB], boff[NB], ctile[NB], coff[NB];
    __shared__ uint8_t bseg[NB], cseg[NB];
    __shared__ int s_iml[NB], s_sl[NB];
    const int tid = threadIdx.x;

    if (tid < NB) s_iml[tid] = im_len[tid];
    else if (tid < 2 * NB) s_sl[tid - NB] = s_len[tid - NB];
    if (tid == 32) { g_tick = 0; g_done = 0; }
    __syncthreads();

    if (tid == 0) {   // serial next-fit scans: SMEM-only writes
        int tile = 0, off = 0, seg = 0;
        #pragma unroll 4
        for (int b = 0; b < NB; ++b) {
            int L = s_iml[b] - 1;
            if (off + L > 144) { ++tile; off = 0; seg = 0; }
            btile[b] = (int16_t)tile; boff[b] = (int16_t)off; bseg[b] = (uint8_t)seg;
            off += L; ++seg;
        }
        g_nmt = tile + 1;
    } else if (tid == 64) {
        int tile = 0, off = 0, seg = 0;
        #pragma unroll 4
        for (int c = 0; c < NB; ++c) {
            int L = s_sl[c] - 3;
            if (off + L > 128) { ++tile; off = 0; seg = 0; }
            ctile[c] = (int16_t)tile; coff[c] = (int16_t)off; cseg[c] = (uint8_t)seg;
            off += L; ++seg;
        }
        g_nnt = tile + 1;
    }
    __syncthreads();
    if (tid == 0) g_T = g_nmt * g_nnt;

    if (tid < NB) {                       // image-side table writes (O(1) each)
        int b = tid, L = s_iml[b] - 1;
        int tl = btile[b], sg = bseg[b], of = boff[b];
        g_tile_b[tl * 36 + sg]   = (int16_t)b;
        g_tile_off[tl * 36 + sg] = (int16_t)of;
        g_tile_len[tl * 36 + sg] = (uint8_t)L;
        if (b == NB - 1 || btile[b + 1] != tl) g_tile_nb[tl] = (uint8_t)(sg + 1);
    } else if (tid < 2 * NB) {            // sentence-side table writes
        int c = tid - NB, L = s_sl[c] - 3;
        int tl = ctile[c], sg = cseg[c], of = coff[c];
        g_tile_c[tl * 26 + sg]    = (int16_t)c;
        g_tile_coff[tl * 26 + sg] = (int16_t)of;
        g_tile_clen[tl * 26 + sg] = (uint8_t)L;
        if (c == NB - 1 || ctile[c + 1] != tl) g_tile_nc[tl] = (uint8_t)(sg + 1);
    }
}

// ---------------------------------------------------------------------------
// Stage 1: pack fp32 -> s8; each block resolves its row via segment match
// ---------------------------------------------------------------------------
__global__ void pack_kernel(const float* __restrict__ im, const float* __restrict__ sq) {
    const int row = blockIdx.x;
    const int tid = threadIdx.x;

    if (row < 16) {  // zero g_S
        reinterpret_cast<float4*>(g_S)[row * 256 + tid] = make_float4(0.f, 0.f, 0.f, 0.f);
    }

    __shared__ int s_n, s_sel, s_item, s_pos;

    const float* src = nullptr;
    int8_t* dst;
    if (row < AROWS) {
        if (row >= g_nmt * 144) return;
        const int tl = row / 144, local = row - tl * 144;
        if (tid == 0) { s_n = g_tile_nb[tl]; s_sel = -1; }
        __syncthreads();
        if (tid < s_n) {
            int of = g_tile_off[tl * 36 + tid];
            int L  = g_tile_len[tl * 36 + tid];
            if (local >= of && local < of + L) {
                s_item = g_tile_b[tl * 36 + tid];
                s_pos  = local - of;
                s_sel  = tid;
            }
        }
        __syncthreads();
        dst = g_A + (size_t)row * DIM;
        if (s_sel >= 0) src = im + (size_t)(s_item * 37 + s_pos + 1) * DIM;
    } else {
        const int rb = row - AROWS;
        if (rb >= g_nnt * 128) return;
        const int tl = rb / 128, local = rb - tl * 128;
        if (tid == 0) { s_n = g_tile_nc[tl]; s_sel = -1; }
        __syncthreads();
        if (tid < s_n) {
            int of = g_tile_coff[tl * 26 + tid];
            int L  = g_tile_clen[tl * 26 + tid];
            if (local >= of && local < of + L) {
                s_item = g_tile_c[tl * 26 + tid];
                s_pos  = local - of;
                s_sel  = tid;
            }
        }
        __syncthreads();
        dst = g_B + (size_t)rb * DIM;
        if (s_sel >= 0) src = sq + (size_t)(s_item * 53 + s_pos + 1) * DIM;
        if (tid == 0) g_colseg[rb] = (s_sel >= 0) ? (uint8_t)s_sel : 0xFF;
    }
    const int k = tid * 4;
    uint32_t packed = 0u;
    if (src) {
        float4 v = *reinterpret_cast<const float4*>(src + k);
        int q0 = q8(v.x), q1 = q8(v.y), q2 = q8(v.z), q3 = q8(v.w);
        packed = (uint32_t)(q0 & 0xFF) | ((uint32_t)(q1 & 0xFF) << 8) |
                 ((uint32_t)(q2 & 0xFF) << 16) | ((uint32_t)(q3 & 0xFF) << 24);
    }
    *reinterpret_cast<uint32_t*>(dst + k) = packed;
}

// ---------------------------------------------------------------------------
// Stage 2: persistent-CTA s8 GEMM, 3-stage single-sync pipeline, fused loss
// ---------------------------------------------------------------------------
static constexpr int STAGE_BYTES = 21760;
static constexpr int ROW_BYTES   = 80;
static constexpr int B_SM_OFF    = 11520;
static constexpr int SM_RED      = 65280;               // [144][67] f32 = 38592
static constexpr int SM_PAIRS    = 103872;              // [36][26]  f32 = 3744
static constexpr int SM_SEGB     = 107616;              // [36] i16
static constexpr int SM_SEGCL    = 107688;              // [36] u8
static constexpr int SM_SEGOFF   = 107728;              // [36] i16
static constexpr int SM_SEGLEN   = 107800;              // [36] u8
static constexpr int SM_CS       = 107840;              // [64] u8
static constexpr int SM_TIDX     = 107904;              // int
static constexpr int SMEM_TOTAL  = 107968;              // x2 = 215936 < 228K/SM
static constexpr int NCH = 16;
static constexpr int PCTAS = 296;

__global__ __launch_bounds__(384, 2)
void mma_kernel(const int* __restrict__ im_len, const int* __restrict__ s_len,
                float* __restrict__ out) {
    extern __shared__ __align__(16) char sm[];
    const uint32_t sb = smem_u32(sm);
    const int tid  = threadIdx.x;
    const int lane = tid & 31;
    const int wid  = tid >> 5;

    const int wm = wid >> 2;
    const int wn = wid & 3;
    const int group = lane >> 2;
    const int tig   = lane & 3;
    const int mbase = wm * 48;
    const int nbase = wn * 32;

    const int nnt = g_nnt;
    const int T   = g_T;
    int* s_t = reinterpret_cast<int*>(sm + SM_TIDX);

    // stage: 0..2 ring; chunk k lives in stage k%3
    auto load_stage = [&](int stage, int chunk, const int8_t* Ap, const int8_t* Bp) {
        const int k0 = chunk * 64;
        const uint32_t base = sb + stage * STAGE_BYTES;
        #pragma unroll
        for (int it = 0; it < 3; ++it) {
            int idx = tid + it * 384;
            if (idx < 576) {
                int row = idx >> 2, seg = idx & 3;
                cpa16(base + row * ROW_BYTES + seg * 16, Ap + row * DIM + k0 + seg * 16);
            } else if (idx < 1088) {
                int u = idx - 576;
                int row = u >> 2, seg = u & 3;
                cpa16(base + B_SM_OFF + row * ROW_BYTES + seg * 16, Bp + row * DIM + k0 + seg * 16);
            }
        }
    };

    // first ticket + prologue loads (chunks 0,1 into stages 0,1)
    if (tid == 0) *s_t = atomicAdd(&g_tick, 1);
    __syncthreads();
    int t = *s_t;
    if (t < T) {
        const int mt0 = t / nnt, nt0 = t - (t / nnt) * nnt;
        const int8_t* Ap = g_A + (size_t)mt0 * (144 * DIM);
        const int8_t* Bp = g_B + (size_t)nt0 * (128 * DIM);
        load_stage(0, 0, Ap, Bp); CPA_COMMIT();
        load_stage(1, 1, Ap, Bp); CPA_COMMIT();
    }

    while (t < T) {
        const int mt = t / nnt;
        const int nt = t - mt * nnt;
        const int8_t* Ap = g_A + (size_t)mt * (144 * DIM);
        const int8_t* Bp = g_B + (size_t)nt * (128 * DIM);

        int acc[3][4][4];
        #pragma unroll
        for (int mi = 0; mi < 3; ++mi)
            #pragma unroll
            for (int ni = 0; ni < 4; ++ni)
                #pragma unroll
                for (int q = 0; q < 4; ++q) acc[mi][ni][q] = 0;

        // 3-stage single-sync mainloop:
        //   wait1 (own chunk-ch copies done; ch+1 stays pending)
        //   sync  (ALL threads' ch copies visible; all warps past compute ch-1)
        //   issue ch+2 into stage (ch+2)%3 == (ch-1)%3 (freed by the sync)
        //   compute ch (stage ch%3), no trailing sync
        for (int ch = 0; ch < NCH; ++ch) {
            CPA_WAIT1();
            __syncthreads();
            if (ch + 2 < NCH) { load_stage((ch + 2) % 3, ch + 2, Ap, Bp); CPA_COMMIT(); }
            const uint32_t As = sb + (ch % 3) * STAGE_BYTES;
            const uint32_t Bs = As + B_SM_OFF;
            #pragma unroll
            for (int kk = 0; kk < 2; ++kk) {
                const uint32_t kb = kk * 32;
                uint32_t a[3][4];
                #pragma unroll
                for (int mi = 0; mi < 3; ++mi) {
                    uint32_t r0 = As + (mbase + mi * 16 + group) * ROW_BYTES + kb + tig * 4;
                    uint32_t r1 = r0 + 8 * ROW_BYTES;
                    a[mi][0] = lds32(r0);
                    a[mi][1] = lds32(r1);
                    a[mi][2] = lds32(r0 + 16);
                    a[mi][3] = lds32(r1 + 16);
                }
                #pragma unroll
                for (int ni = 0; ni < 4; ++ni) {
                    uint32_t rb = Bs + (nbase + ni * 8 + group) * ROW_BYTES + kb + tig * 4;
                    uint32_t b0 = lds32(rb);
                    uint32_t b1 = lds32(rb + 16);
                    #pragma unroll
                    for (int mi = 0; mi < 3; ++mi)
                        mma_s8(acc[mi][ni][0], acc[mi][ni][1], acc[mi][ni][2], acc[mi][ni][3],
                               a[mi][0], a[mi][1], a[mi][2], a[mi][3], b0, b1);
                }
            }
        }
        __syncthreads();   // all warps done reading stages for this tile

        // fetch next ticket and prefetch its chunks 0,1 BEFORE epilogue
        if (tid == 0) *s_t = atomicAdd(&g_tick, 1);
        __syncthreads();
        const int t2 = *s_t;
        if (t2 < T) {
            const int mt2 = t2 / nnt, nt2 = t2 - (t2 / nnt) * nnt;
            const int8_t* Ap2 = g_A + (size_t)mt2 * (144 * DIM);
            const int8_t* Bp2 = g_B + (size_t)nt2 * (128 * DIM);
            load_stage(0, 0, Ap2, Bp2); CPA_COMMIT();
            load_stage(1, 1, Ap2, Bp2); CPA_COMMIT();
        }

        // ---------------- epilogue (red region disjoint from stages) -------
        float*   red    = reinterpret_cast<float*>(sm + SM_RED);
        float*   pairS  = reinterpret_cast<float*>(sm + SM_PAIRS);
        int16_t* segb   = reinterpret_cast<int16_t*>(sm + SM_SEGB);
        uint8_t* segcl  = reinterpret_cast<uint8_t*>(sm + SM_SEGCL);
        int16_t* segoff = reinterpret_cast<int16_t*>(sm + SM_SEGOFF);
        uint8_t* seglen = reinterpret_cast<uint8_t*>(sm + SM_SEGLEN);
        uint8_t* cs_sm  = reinterpret_cast<uint8_t*>(sm + SM_CS);

        const int nbv = g_tile_nb[mt];
        for (int i = tid; i < 36 * 26; i += 384) pairS[i] = 0.f;
        if (tid < nbv) {
            int s = tid;
            segb[s]   = g_tile_b[mt * 36 + s];
            segoff[s] = g_tile_off[mt * 36 + s];
            int L = g_tile_len[mt * 36 + s];
            seglen[s] = (uint8_t)L;
            segcl[s]  = (L < 36) ? 1 : 0;
        }

        #pragma unroll
        for (int h = 0; h < 2; ++h) {
            if (tid < 64) cs_sm[tid] = g_colseg[nt * 128 + h * 64 + tid];
            __syncthreads();
            if ((wn >> 1) == h) {
                #pragma unroll
                for (int mi = 0; mi < 3; ++mi)
                    #pragma unroll
                    for (int half = 0; half < 2; ++half) {
                        const int r = mbase + mi * 16 + group + half * 8;
                        #pragma unroll
                        for (int ni = 0; ni < 4; ++ni) {
                            int col = nbase + ni * 8 + tig * 2 - h * 64;
                            red[r * 67 + col]     = (float)acc[mi][ni][half * 2 + 0] * INV2;
                            red[r * 67 + col + 1] = (float)acc[mi][ni][half * 2 + 1] * INV2;
                        }
                    }
            }
            __syncthreads();

            const int col = tid & 63;
            const int cs = cs_sm[col];
            if (cs != 0xFF) {
                for (int s = tid >> 6; s < nbv; s += 6) {
                    const int r0 = segoff[s];
                    const int L  = seglen[s];
                    const float* cp = red + r0 * 67 + col;
                    float m = cp[0];
                    for (int r = 1; r < L; ++r) m = fmaxf(m, cp[r * 67]);
                    if (segcl[s]) m = fmaxf(m, 0.f);
                    atomicAdd(&pairS[s * 26 + cs], m);
                }
            }
            __syncthreads();
        }

        const int ncv = g_tile_nc[nt];
        for (int idx = tid; idx < nbv * ncv; idx += 384) {
            int s = idx / ncv, cs = idx - s * ncv;
            int b = segb[s];
            int c = g_tile_c[nt * 26 + cs];
            g_S[b * NB + c] = pairS[s * 26 + cs];
        }
        __syncthreads();
        t = t2;
    }

    // ---------------- fused loss: last CTA reduces g_S ----------------
    __threadfence();
    __syncthreads();
    if (tid == 0) {
        int old = atomicAdd(&g_done, 1);
        *s_t = (old == PCTAS - 1) ? 1 : 0;
    }
    __syncthreads();
    if (*s_t) {
        __threadfence();
        float* diag = reinterpret_cast<float*>(sm);
        float* wsum = reinterpret_cast<float*>(sm) + 128;
        if (tid < NB) diag[tid] = g_S[tid * (NB + 1)];
        __syncthreads();
        float acc = 0.f;
        for (int idx = tid; idx < NB * NB; idx += 384) {
            int b = idx >> 7, c = idx & 127;
            if (b != c) {
                float sc = g_S[idx];
                acc += fmaxf(0.f, 0.2f + sc - diag[b]) + fmaxf(0.f, 0.2f + sc - diag[c]);
            }
        }
        #pragma unroll
        for (int o = 16; o; o >>= 1) acc += __shfl_xor_sync(0xffffffffu, acc, o);
        if (lane == 0) wsum[wid] = acc;
        __syncthreads();
        if (wid == 0) {
            float v = (lane < 12) ? wsum[lane] : 0.f;
            #pragma unroll
            for (int o = 16; o; o >>= 1) v += __shfl_xor_sync(0xffffffffu, v, o);
            if (lane == 0) out[0] = v;
        }
    }
}

// ---------------------------------------------------------------------------
extern "C" void kernel_launch(void* const* d_in, const int* in_sizes, int n_in,
                              void* d_out, int out_size) {
    (void)in_sizes; (void)n_in; (void)out_size;
    const float* im   = (const float*)d_in[0];
    const float* sq   = (const float*)d_in[1];
    const int* im_len = (const int*)d_in[2];
    const int* s_len  = (const int*)d_in[3];

    cudaFuncSetAttribute(mma_kernel, cudaFuncAttributeMaxDynamicSharedMemorySize, SMEM_TOTAL);

    meta_kernel<<<1, 256>>>(im_len, s_len);
    pack_kernel<<<AROWS + BROWS, 256>>>(im, sq);
    mma_kernel<<<PCTAS, 384, SMEM_TOTAL>>>(im_len, s_len, (float*)d_out);
}